// round 6
// baseline (speedup 1.0000x reference)
#include <cuda_runtime.h>
#include <math.h>
#include <stdint.h>

// ---------------- problem constants ----------------
#define BB    64
#define HH    28
#define WW    28
#define CC    384
#define WS    7
#define SHIFT 3
#define NHD   12
#define HD    32
#define HID   1536
#define NWIN  16
#define NTOK  49
#define TOK   50176
#define NWINS 1024
#define ATT_SCALE 0.17677669529663687f

// ---------------- static scratch ----------------
__device__ float g_xw [(size_t)TOK * CC];
__device__ float g_qkv[(size_t)TOK * 3 * CC];
__device__ float g_ow [(size_t)TOK * CC];
__device__ float g_y  [(size_t)TOK * CC];
__device__ float g_ln2[(size_t)TOK * CC];
__device__ float g_mid[(size_t)TOK * HID];
__device__ int   g_dmap[TOK];

// ---------------- LayerNorm, float4 path (mode 1 fuses shift + window gather) ----------------
__global__ __launch_bounds__(96) void ln_kernel(
    const float* __restrict__ x, const float* __restrict__ g,
    const float* __restrict__ b, float* __restrict__ out, int mode)
{
    int r = blockIdx.x;
    int src = r;
    if (mode == 1) {
        int win  = r / NTOK;
        int n    = r - win * NTOK;
        int bidx = win >> 4;
        int widx = win & 15;
        int wi = widx >> 2, wj = widx & 3;
        int ph = n / WS, pw = n - ph * WS;
        int h = (wi * WS + ph + SHIFT) % HH;
        int w = (wj * WS + pw + SHIFT) % WW;
        src = bidx * (HH * WW) + h * WW + w;
        if (threadIdx.x == 0) g_dmap[r] = src;
    }
    int t = threadIdx.x;            // 0..95, 96*4 = 384
    const float4* xr = (const float4*)(x + (size_t)src * CC);
    float4 v = xr[t];
    float s  = v.x + v.y + v.z + v.w;
    float s2 = v.x * v.x + v.y * v.y + v.z * v.z + v.w * v.w;
    #pragma unroll
    for (int o = 16; o; o >>= 1) {
        s  += __shfl_xor_sync(0xffffffffu, s,  o);
        s2 += __shfl_xor_sync(0xffffffffu, s2, o);
    }
    __shared__ float sh[3], sh2[3];
    int warp = t >> 5, lane = t & 31;
    if (lane == 0) { sh[warp] = s; sh2[warp] = s2; }
    __syncthreads();
    if (t == 0) {
        float S  = sh[0] + sh[1] + sh[2];
        float S2 = sh2[0] + sh2[1] + sh2[2];
        float mu  = S * (1.0f / CC);
        float var = S2 * (1.0f / CC) - mu * mu;
        sh[0]  = mu;
        sh2[0] = rsqrtf(var + 1e-5f);
    }
    __syncthreads();
    float mu = sh[0], inv = sh2[0];
    float4 gg = ((const float4*)g)[t];
    float4 bb = ((const float4*)b)[t];
    float4 o4;
    o4.x = (v.x - mu) * inv * gg.x + bb.x;
    o4.y = (v.y - mu) * inv * gg.y + bb.y;
    o4.z = (v.z - mu) * inv * gg.z + bb.z;
    o4.w = (v.w - mu) * inv * gg.w + bb.w;
    ((float4*)(out + (size_t)r * CC))[t] = o4;
}

// ---------------- tf32 tensor-core GEMM, 256x128 tile, 4-stage cp.async ----------------
// 8 warps in 4m x 2n, warp tile 64x64 (4 m-frags x 8 n-frags of m16n8k8).
// A:[M,K] row-major, B:[K,N] row-major, fp32 in smem (HMMA.tf32 truncates in HW).
#define GBM 256
#define GBN 128
#define GBK 16
#define AST 20          // A smem row stride (floats)
#define BST 136         // B smem row stride (floats)
#define STAGES 4
#define A_STG (GBM * AST)   // 5120 floats
#define B_STG (GBK * BST)   // 2176 floats
#define SMEM_BYTES (STAGES * (A_STG + B_STG) * 4)   // 116736

__device__ __forceinline__ void cp16(uint32_t s, const void* g) {
    asm volatile("cp.async.cg.shared.global [%0], [%1], 16;" :: "r"(s), "l"(g));
}

__global__ __launch_bounds__(256, 1) void mma_gemm(
    const float* __restrict__ A, const float* __restrict__ Bm,
    const float* __restrict__ bias, float* __restrict__ Cc,
    const float* __restrict__ addend, const int* __restrict__ rowmap,
    int M, int Nn, int K, int act)
{
    extern __shared__ float sm[];
    float* As = sm;
    float* Bs = sm + STAGES * A_STG;
    uint32_t as_base = (uint32_t)__cvta_generic_to_shared(As);
    uint32_t bs_base = (uint32_t)__cvta_generic_to_shared(Bs);

    int tid  = threadIdx.x;
    int warp = tid >> 5, lane = tid & 31;
    int g    = lane >> 2, t4 = lane & 3;
    int wm   = warp >> 1, wn = warp & 1;     // 4 x 2
    int tile_m = blockIdx.y * GBM;
    int tile_n = blockIdx.x * GBN;
    int nk = K / GBK;

    // copy coordinates: A = 1024 16B chunks (4/thread), B = 512 (2/thread)
    int amr[4], akc[4], bkr[2], bnc[2];
    #pragma unroll
    for (int i = 0; i < 4; i++) {
        int c = tid + i * 256;
        amr[i] = c >> 2;  akc[i] = (c & 3) * 4;
    }
    #pragma unroll
    for (int i = 0; i < 2; i++) {
        int c = tid + i * 256;
        bkr[i] = c >> 5;  bnc[i] = (c & 31) * 4;
    }

    auto issue = [&](int tile) {
        int k0 = tile * GBK;
        int s  = tile & (STAGES - 1);
        uint32_t a0 = as_base + (uint32_t)(s * A_STG) * 4u;
        uint32_t b0 = bs_base + (uint32_t)(s * B_STG) * 4u;
        #pragma unroll
        for (int i = 0; i < 4; i++)
            cp16(a0 + (uint32_t)(amr[i] * AST + akc[i]) * 4u,
                 &A[(size_t)(tile_m + amr[i]) * K + k0 + akc[i]]);
        #pragma unroll
        for (int i = 0; i < 2; i++)
            cp16(b0 + (uint32_t)(bkr[i] * BST + bnc[i]) * 4u,
                 &Bm[(size_t)(k0 + bkr[i]) * Nn + tile_n + bnc[i]]);
        asm volatile("cp.async.commit_group;");
    };

    float acc[4][8][4];
    #pragma unroll
    for (int i = 0; i < 4; i++)
        #pragma unroll
        for (int j = 0; j < 8; j++)
            #pragma unroll
            for (int q = 0; q < 4; q++) acc[i][j][q] = 0.0f;

    #pragma unroll
    for (int s = 0; s < STAGES - 1; s++) issue(s);

    for (int it = 0; it < nk; it++) {
        asm volatile("cp.async.wait_group %0;" :: "n"(STAGES - 2));
        __syncthreads();
        int s = it & (STAGES - 1);
        const float* Ab = As + s * A_STG;
        const float* Bb = Bs + s * B_STG;
        int nxt = it + STAGES - 1;
        if (nxt < nk) issue(nxt);
        else asm volatile("cp.async.commit_group;");

        #pragma unroll
        for (int ks = 0; ks < 2; ks++) {
            int kb = ks * 8;
            unsigned a[4][4], bfr[8][2];
            #pragma unroll
            for (int mt = 0; mt < 4; mt++) {
                int mrow = wm * 64 + mt * 16;
                a[mt][0] = __float_as_uint(Ab[(mrow + g)     * AST + kb + t4]);
                a[mt][1] = __float_as_uint(Ab[(mrow + g + 8) * AST + kb + t4]);
                a[mt][2] = __float_as_uint(Ab[(mrow + g)     * AST + kb + t4 + 4]);
                a[mt][3] = __float_as_uint(Ab[(mrow + g + 8) * AST + kb + t4 + 4]);
            }
            #pragma unroll
            for (int nt = 0; nt < 8; nt++) {
                int ncol = wn * 64 + nt * 8;
                bfr[nt][0] = __float_as_uint(Bb[(kb + t4)     * BST + ncol + g]);
                bfr[nt][1] = __float_as_uint(Bb[(kb + t4 + 4) * BST + ncol + g]);
            }
            #pragma unroll
            for (int mt = 0; mt < 4; mt++)
                #pragma unroll
                for (int nt = 0; nt < 8; nt++) {
                    asm volatile(
                        "mma.sync.aligned.m16n8k8.row.col.f32.tf32.tf32.f32 "
                        "{%0,%1,%2,%3},{%4,%5,%6,%7},{%8,%9},{%0,%1,%2,%3};"
                        : "+f"(acc[mt][nt][0]), "+f"(acc[mt][nt][1]),
                          "+f"(acc[mt][nt][2]), "+f"(acc[mt][nt][3])
                        : "r"(a[mt][0]), "r"(a[mt][1]), "r"(a[mt][2]), "r"(a[mt][3]),
                          "r"(bfr[nt][0]), "r"(bfr[nt][1]));
                }
        }
    }

    // epilogue
    #pragma unroll
    for (int mt = 0; mt < 4; mt++) {
        int r0 = tile_m + wm * 64 + mt * 16 + g;
        int r1 = r0 + 8;
        int o0 = rowmap ? rowmap[r0] : r0;
        int o1 = rowmap ? rowmap[r1] : r1;
        #pragma unroll
        for (int nt = 0; nt < 8; nt++) {
            int c0 = tile_n + wn * 64 + nt * 8 + 2 * t4;
            #pragma unroll
            for (int q = 0; q < 4; q++) {
                int row = (q < 2) ? o0 : o1;
                int col = c0 + (q & 1);
                float v = acc[mt][nt][q] + bias[col];
                if (act == 1) v = 0.5f * v * (1.0f + erff(v * 0.70710678118654752f));
                size_t off = (size_t)row * Nn + col;
                if (addend) v += addend[off];
                Cc[off] = v;
            }
        }
    }
}

// ---------------- windowed attention ----------------
__global__ __launch_bounds__(256) void attn_kernel(
    const float* __restrict__ rpb, float* __restrict__ ow)
{
    int head = blockIdx.x;
    int win  = blockIdx.y;
    __shared__ __align__(16) float qs[NTOK * HD];
    __shared__ __align__(16) float ks[NTOK * HD];
    __shared__ __align__(16) float vs[NTOK * HD];
    __shared__ float S[NTOK * 52];

    int tid = threadIdx.x;
    const float* base = g_qkv + (size_t)win * NTOK * (3 * CC);

    for (int idx = tid; idx < NTOK * HD; idx += 256) {
        int n = idx >> 5, d = idx & 31;
        const float* row = base + (size_t)n * (3 * CC) + head * HD + d;
        qs[idx] = row[0] * ATT_SCALE;
        ks[idx] = row[CC];
        vs[idx] = row[2 * CC];
    }
    __syncthreads();

    int widx = win & 15;
    int wi = widx >> 2, wj = widx & 3;

    if (tid < 245) {
        int n  = tid / 5;
        int ms = tid - n * 5;
        float4 q[8];
        const float4* q4 = (const float4*)&qs[n * HD];
        #pragma unroll
        for (int i = 0; i < 8; i++) q[i] = q4[i];

        int in_ = n / WS, jn = n - in_ * WS;
        int hn = wi * WS + in_, wn_ = wj * WS + jn;
        int vn = (hn < HH - WS ? 0 : (hn < HH - SHIFT ? 1 : 2)) * 3
               + (wn_ < WW - WS ? 0 : (wn_ < WW - SHIFT ? 1 : 2));

        for (int m = ms; m < NTOK; m += 5) {
            const float4* k4 = (const float4*)&ks[m * HD];
            float dot = 0.0f;
            #pragma unroll
            for (int i = 0; i < 8; i++) {
                float4 kk = k4[i];
                dot += q[i].x * kk.x + q[i].y * kk.y + q[i].z * kk.z + q[i].w * kk.w;
            }
            int im = m / WS, jm = m - im * WS;
            int rel = (in_ - im + WS - 1) * (2 * WS - 1) + (jn - jm + WS - 1);
            dot += rpb[rel * NHD + head];
            int hm = wi * WS + im, wm = wj * WS + jm;
            int vm = (hm < HH - WS ? 0 : (hm < HH - SHIFT ? 1 : 2)) * 3
                   + (wm < WW - WS ? 0 : (wm < WW - SHIFT ? 1 : 2));
            if (vn != vm) dot -= 100.0f;
            S[n * 52 + m] = dot;
        }
    }
    __syncthreads();

    int warp = tid >> 5, lane = tid & 31;
    for (int n = warp; n < NTOK; n += 8) {
        float mx = -1e30f;
        for (int m = lane; m < NTOK; m += 32) mx = fmaxf(mx, S[n * 52 + m]);
        #pragma unroll
        for (int o = 16; o; o >>= 1) mx = fmaxf(mx, __shfl_xor_sync(0xffffffffu, mx, o));
        float sum = 0.0f;
        for (int m = lane; m < NTOK; m += 32) {
            float e = __expf(S[n * 52 + m] - mx);
            S[n * 52 + m] = e;
            sum += e;
        }
        #pragma unroll
        for (int o = 16; o; o >>= 1) sum += __shfl_xor_sync(0xffffffffu, sum, o);
        float inv = 1.0f / sum;
        for (int m = lane; m < NTOK; m += 32) S[n * 52 + m] *= inv;
    }
    __syncthreads();

    const float4* v4 = (const float4*)vs;
    for (int idx = tid; idx < NTOK * 8; idx += 256) {
        int n = idx >> 3, dq = idx & 7;
        float4 s4 = make_float4(0.f, 0.f, 0.f, 0.f);
        for (int m = 0; m < NTOK; m++) {
            float p = S[n * 52 + m];
            float4 v = v4[m * 8 + dq];
            s4.x += p * v.x; s4.y += p * v.y; s4.z += p * v.z; s4.w += p * v.w;
        }
        float* orow = ow + ((size_t)win * NTOK + n) * CC + head * HD + dq * 4;
        orow[0] = s4.x; orow[1] = s4.y; orow[2] = s4.z; orow[3] = s4.w;
    }
}

// ---------------- launch ----------------
extern "C" void kernel_launch(void* const* d_in, const int* in_sizes, int n_in,
                              void* d_out, int out_size)
{
    const float* x      = (const float*)d_in[0];
    const float* qkv_w  = (const float*)d_in[1];
    const float* qkv_b  = (const float*)d_in[2];
    const float* proj_w = (const float*)d_in[3];
    const float* proj_b = (const float*)d_in[4];
    const float* rpb    = (const float*)d_in[5];
    const float* n1g    = (const float*)d_in[6];
    const float* n1b    = (const float*)d_in[7];
    const float* n2g    = (const float*)d_in[8];
    const float* n2b    = (const float*)d_in[9];
    const float* fc1_w  = (const float*)d_in[10];
    const float* fc1_b  = (const float*)d_in[11];
    const float* fc2_w  = (const float*)d_in[12];
    const float* fc2_b  = (const float*)d_in[13];
    float* out = (float*)d_out;

    float *xw, *qkv, *ow, *y, *ln2, *mid; int* dmap;
    cudaGetSymbolAddress((void**)&xw,   g_xw);
    cudaGetSymbolAddress((void**)&qkv,  g_qkv);
    cudaGetSymbolAddress((void**)&ow,   g_ow);
    cudaGetSymbolAddress((void**)&y,    g_y);
    cudaGetSymbolAddress((void**)&ln2,  g_ln2);
    cudaGetSymbolAddress((void**)&mid,  g_mid);
    cudaGetSymbolAddress((void**)&dmap, g_dmap);

    cudaFuncSetAttribute(mma_gemm, cudaFuncAttributeMaxDynamicSharedMemorySize, SMEM_BYTES);

    // 1. LN1 + shift + window partition
    ln_kernel<<<TOK, 96>>>(x, n1g, n1b, xw, 1);

    // 2. QKV: (50176,384) @ (384,1152)
    mma_gemm<<<dim3((3 * CC) / GBN, TOK / GBM), 256, SMEM_BYTES>>>(
        xw, qkv_w, qkv_b, qkv, nullptr, nullptr, TOK, 3 * CC, CC, 0);

    // 3. Windowed attention
    attn_kernel<<<dim3(NHD, NWINS), 256>>>(rpb, ow);

    // 4. Proj + window reverse + residual
    mma_gemm<<<dim3(CC / GBN, TOK / GBM), 256, SMEM_BYTES>>>(
        ow, proj_w, proj_b, y, x, dmap, TOK, CC, CC, 0);

    // 5. LN2
    ln_kernel<<<TOK, 96>>>(y, n2g, n2b, ln2, 0);

    // 6. FC1 + GELU: (50176,384) @ (384,1536)
    mma_gemm<<<dim3(HID / GBN, TOK / GBM), 256, SMEM_BYTES>>>(
        ln2, fc1_w, fc1_b, mid, nullptr, nullptr, TOK, HID, CC, 1);

    // 7. FC2 + residual: (50176,1536) @ (1536,384)
    mma_gemm<<<dim3(CC / GBN, TOK / GBM), 256, SMEM_BYTES>>>(
        mid, fc2_w, fc2_b, out, y, nullptr, TOK, CC, HID, 0);
}

// round 7
// speedup vs baseline: 1.3625x; 1.3625x over previous
#include <cuda_runtime.h>
#include <cuda_fp16.h>
#include <math.h>
#include <stdint.h>

// ---------------- problem constants ----------------
#define BB    64
#define HH    28
#define WW    28
#define CC    384
#define WS    7
#define SHIFT 3
#define NHD   12
#define HD    32
#define HID   1536
#define NWIN  16
#define NTOK  49
#define TOK   50176
#define NWINS 1024
#define ATT_SCALE 0.17677669529663687f

// ---------------- static scratch ----------------
__device__ __half g_xw [(size_t)TOK * CC];       // LN1 out (fp16, GEMM A)
__device__ float  g_qkv[(size_t)TOK * 3 * CC];   // QKV out (fp32, attention input)
__device__ __half g_ow [(size_t)TOK * CC];       // attention out (fp16, GEMM A)
__device__ float  g_y  [(size_t)TOK * CC];       // post-attn residual (fp32)
__device__ __half g_ln2[(size_t)TOK * CC];       // LN2 out (fp16)
__device__ __half g_mid[(size_t)TOK * HID];      // FC1+GELU out (fp16)
__device__ int    g_dmap[TOK];
// fp16 transposed weights [N][K]
__device__ __half g_wh_qkv [(size_t)(3 * CC) * CC];
__device__ __half g_wh_proj[(size_t)CC * CC];
__device__ __half g_wh_fc1 [(size_t)HID * CC];
__device__ __half g_wh_fc2 [(size_t)CC * HID];

// ---------------- weight convert + transpose: fp32 [K][N] -> fp16 [N][K] ----------------
__global__ __launch_bounds__(256) void convw_kernel(
    const float* __restrict__ in, __half* __restrict__ out, int K, int N)
{
    __shared__ float t[32][33];
    int bx = blockIdx.x * 32, by = blockIdx.y * 32;   // bx: N, by: K
    int tx = threadIdx.x, ty = threadIdx.y;
    #pragma unroll
    for (int i = 0; i < 32; i += 8)
        t[ty + i][tx] = in[(size_t)(by + ty + i) * N + bx + tx];
    __syncthreads();
    #pragma unroll
    for (int i = 0; i < 32; i += 8)
        out[(size_t)(bx + ty + i) * K + by + tx] = __float2half_rn(t[tx][ty + i]);
}

// ---------------- LayerNorm -> fp16 (mode 1 fuses shift + window gather) ----------------
__global__ __launch_bounds__(96) void ln_kernel(
    const float* __restrict__ x, const float* __restrict__ g,
    const float* __restrict__ b, __half* __restrict__ out, int mode)
{
    int r = blockIdx.x;
    int src = r;
    if (mode == 1) {
        int win  = r / NTOK;
        int n    = r - win * NTOK;
        int bidx = win >> 4;
        int widx = win & 15;
        int wi = widx >> 2, wj = widx & 3;
        int ph = n / WS, pw = n - ph * WS;
        int h = (wi * WS + ph + SHIFT) % HH;
        int w = (wj * WS + pw + SHIFT) % WW;
        src = bidx * (HH * WW) + h * WW + w;
        if (threadIdx.x == 0) g_dmap[r] = src;
    }
    int t = threadIdx.x;            // 0..95
    const float4* xr = (const float4*)(x + (size_t)src * CC);
    float4 v = xr[t];
    float s  = v.x + v.y + v.z + v.w;
    float s2 = v.x * v.x + v.y * v.y + v.z * v.z + v.w * v.w;
    #pragma unroll
    for (int o = 16; o; o >>= 1) {
        s  += __shfl_xor_sync(0xffffffffu, s,  o);
        s2 += __shfl_xor_sync(0xffffffffu, s2, o);
    }
    __shared__ float sh[3], sh2[3];
    int warp = t >> 5, lane = t & 31;
    if (lane == 0) { sh[warp] = s; sh2[warp] = s2; }
    __syncthreads();
    if (t == 0) {
        float S  = sh[0] + sh[1] + sh[2];
        float S2 = sh2[0] + sh2[1] + sh2[2];
        float mu  = S * (1.0f / CC);
        float var = S2 * (1.0f / CC) - mu * mu;
        sh[0]  = mu;
        sh2[0] = rsqrtf(var + 1e-5f);
    }
    __syncthreads();
    float mu = sh[0], inv = sh2[0];
    float4 gg = ((const float4*)g)[t];
    float4 bb = ((const float4*)b)[t];
    float4 o4;
    o4.x = (v.x - mu) * inv * gg.x + bb.x;
    o4.y = (v.y - mu) * inv * gg.y + bb.y;
    o4.z = (v.z - mu) * inv * gg.z + bb.z;
    o4.w = (v.w - mu) * inv * gg.w + bb.w;
    __half2* orow = (__half2*)(out + (size_t)r * CC);
    orow[2 * t]     = __floats2half2_rn(o4.x, o4.y);
    orow[2 * t + 1] = __floats2half2_rn(o4.z, o4.w);
}

// ---------------- fp16 tensor-core GEMM (m16n8k16), 4-stage cp.async ----------------
// 128x128 CTA tile, GBK=32 (two k16 steps/iter), 8 warps 2m x 4n, warp tile 64x32.
// A:[M,K] fp16 row-major, Bt:[N,K] fp16 row-major (= col-major B). Smem rows
// of 32 halves padded to 40 (20 words) -> conflict-free frag loads.
#define KC 32
#define WSTR 20                          // words per smem row
#define OP_W (128 * WSTR)                // 2560 words per operand per stage
#define STG_W (2 * OP_W)                 // 5120 words
#define STAGES 4
#define SMEM_BYTES (STAGES * STG_W * 4)  // 81920

__device__ __forceinline__ void cp16(uint32_t s, const void* g) {
    asm volatile("cp.async.cg.shared.global [%0], [%1], 16;" :: "r"(s), "l"(g));
}

__global__ __launch_bounds__(256, 2) void mma_gemm(
    const __half* __restrict__ A, const __half* __restrict__ Bt,
    const float* __restrict__ bias, float* __restrict__ Cf,
    __half* __restrict__ Ch,
    const float* __restrict__ addend, const int* __restrict__ rowmap,
    int M, int Nn, int K, int act)
{
    extern __shared__ uint32_t sw[];
    uint32_t base = (uint32_t)__cvta_generic_to_shared(sw);

    int tid  = threadIdx.x;
    int warp = tid >> 5, lane = tid & 31;
    int g    = lane >> 2, t4 = lane & 3;
    int wm   = warp >> 2, wn = warp & 3;     // 2 x 4
    int tile_m = blockIdx.y * 128;
    int tile_n = blockIdx.x * 128;
    int nk = K / KC;

    // copy coords: 512 16B chunks per operand, 2/thread each
    int rr[2], ch[2];
    #pragma unroll
    for (int i = 0; i < 2; i++) {
        int c = tid + i * 256;
        rr[i] = c >> 2;  ch[i] = c & 3;
    }

    auto issue = [&](int tile) {
        int k0 = tile * KC;
        int s  = tile & (STAGES - 1);
        uint32_t sb = base + (uint32_t)(s * STG_W) * 4u;
        #pragma unroll
        for (int i = 0; i < 2; i++)
            cp16(sb + (uint32_t)(rr[i] * WSTR + ch[i] * 4) * 4u,
                 &A[(size_t)(tile_m + rr[i]) * K + k0 + ch[i] * 8]);
        #pragma unroll
        for (int i = 0; i < 2; i++)
            cp16(sb + (uint32_t)(OP_W + rr[i] * WSTR + ch[i] * 4) * 4u,
                 &Bt[(size_t)(tile_n + rr[i]) * K + k0 + ch[i] * 8]);
        asm volatile("cp.async.commit_group;");
    };

    float acc[4][4][4];
    #pragma unroll
    for (int i = 0; i < 4; i++)
        #pragma unroll
        for (int j = 0; j < 4; j++)
            #pragma unroll
            for (int q = 0; q < 4; q++) acc[i][j][q] = 0.0f;

    #pragma unroll
    for (int s = 0; s < STAGES - 1; s++) issue(s);

    for (int it = 0; it < nk; it++) {
        asm volatile("cp.async.wait_group %0;" :: "n"(STAGES - 2));
        __syncthreads();
        int s = it & (STAGES - 1);
        const uint32_t* Ab = sw + s * STG_W;
        const uint32_t* Bb = Ab + OP_W;
        int nxt = it + STAGES - 1;
        if (nxt < nk) issue(nxt);
        else asm volatile("cp.async.commit_group;");

        #pragma unroll
        for (int ks = 0; ks < 2; ks++) {
            int kw = ks * 8;                  // word offset of this k16 block
            unsigned a[4][4], bfr[4][2];
            #pragma unroll
            for (int mt = 0; mt < 2; mt++) {
                int mrow = wm * 64 + mt * 32; // two 16-row frags per mt pair below
                a[2*mt][0]   = Ab[(mrow + g)      * WSTR + kw + t4];
                a[2*mt][1]   = Ab[(mrow + g + 8)  * WSTR + kw + t4];
                a[2*mt][2]   = Ab[(mrow + g)      * WSTR + kw + t4 + 4];
                a[2*mt][3]   = Ab[(mrow + g + 8)  * WSTR + kw + t4 + 4];
                a[2*mt+1][0] = Ab[(mrow + 16 + g)     * WSTR + kw + t4];
                a[2*mt+1][1] = Ab[(mrow + 16 + g + 8) * WSTR + kw + t4];
                a[2*mt+1][2] = Ab[(mrow + 16 + g)     * WSTR + kw + t4 + 4];
                a[2*mt+1][3] = Ab[(mrow + 16 + g + 8) * WSTR + kw + t4 + 4];
            }
            #pragma unroll
            for (int nt = 0; nt < 4; nt++) {
                int ncol = wn * 32 + nt * 8;
                bfr[nt][0] = Bb[(ncol + g) * WSTR + kw + t4];
                bfr[nt][1] = Bb[(ncol + g) * WSTR + kw + t4 + 4];
            }
            #pragma unroll
            for (int mt = 0; mt < 4; mt++)
                #pragma unroll
                for (int nt = 0; nt < 4; nt++) {
                    asm volatile(
                        "mma.sync.aligned.m16n8k16.row.col.f32.f16.f16.f32 "
                        "{%0,%1,%2,%3},{%4,%5,%6,%7},{%8,%9},{%0,%1,%2,%3};"
                        : "+f"(acc[mt][nt][0]), "+f"(acc[mt][nt][1]),
                          "+f"(acc[mt][nt][2]), "+f"(acc[mt][nt][3])
                        : "r"(a[mt][0]), "r"(a[mt][1]), "r"(a[mt][2]), "r"(a[mt][3]),
                          "r"(bfr[nt][0]), "r"(bfr[nt][1]));
                }
        }
    }

    // epilogue
    #pragma unroll
    for (int mt = 0; mt < 4; mt++) {
        int r0 = tile_m + wm * 64 + mt * 16 + g;
        int r1 = r0 + 8;
        int o0 = rowmap ? rowmap[r0] : r0;
        int o1 = rowmap ? rowmap[r1] : r1;
        #pragma unroll
        for (int nt = 0; nt < 4; nt++) {
            int c0 = tile_n + wn * 32 + nt * 8 + 2 * t4;
            float b0 = bias[c0], b1 = bias[c0 + 1];
            float v0 = acc[mt][nt][0] + b0, v1 = acc[mt][nt][1] + b1;
            float v2 = acc[mt][nt][2] + b0, v3 = acc[mt][nt][3] + b1;
            if (act == 1) {
                v0 = 0.5f * v0 * (1.0f + erff(v0 * 0.70710678118654752f));
                v1 = 0.5f * v1 * (1.0f + erff(v1 * 0.70710678118654752f));
                v2 = 0.5f * v2 * (1.0f + erff(v2 * 0.70710678118654752f));
                v3 = 0.5f * v3 * (1.0f + erff(v3 * 0.70710678118654752f));
            }
            size_t f0 = (size_t)o0 * Nn + c0;
            size_t f1 = (size_t)o1 * Nn + c0;
            if (addend) {
                v0 += addend[f0]; v1 += addend[f0 + 1];
                v2 += addend[f1]; v3 += addend[f1 + 1];
            }
            if (Ch) {
                *(__half2*)&Ch[f0] = __floats2half2_rn(v0, v1);
                *(__half2*)&Ch[f1] = __floats2half2_rn(v2, v3);
            } else {
                Cf[f0] = v0; Cf[f0 + 1] = v1;
                Cf[f1] = v2; Cf[f1 + 1] = v3;
            }
        }
    }
}

// ---------------- windowed attention (fp32 in, fp16 out) ----------------
__global__ __launch_bounds__(256) void attn_kernel(
    const float* __restrict__ rpb, __half* __restrict__ ow)
{
    int head = blockIdx.x;
    int win  = blockIdx.y;
    __shared__ __align__(16) float qs[NTOK * HD];
    __shared__ __align__(16) float ks[NTOK * HD];
    __shared__ __align__(16) float vs[NTOK * HD];
    __shared__ float S[NTOK * 52];

    int tid = threadIdx.x;
    const float* base = g_qkv + (size_t)win * NTOK * (3 * CC);

    for (int idx = tid; idx < NTOK * HD; idx += 256) {
        int n = idx >> 5, d = idx & 31;
        const float* row = base + (size_t)n * (3 * CC) + head * HD + d;
        qs[idx] = row[0] * ATT_SCALE;
        ks[idx] = row[CC];
        vs[idx] = row[2 * CC];
    }
    __syncthreads();

    int widx = win & 15;
    int wi = widx >> 2, wj = widx & 3;

    if (tid < 245) {
        int n  = tid / 5;
        int ms = tid - n * 5;
        float4 q[8];
        const float4* q4 = (const float4*)&qs[n * HD];
        #pragma unroll
        for (int i = 0; i < 8; i++) q[i] = q4[i];

        int in_ = n / WS, jn = n - in_ * WS;
        int hn = wi * WS + in_, wn_ = wj * WS + jn;
        int vn = (hn < HH - WS ? 0 : (hn < HH - SHIFT ? 1 : 2)) * 3
               + (wn_ < WW - WS ? 0 : (wn_ < WW - SHIFT ? 1 : 2));

        for (int m = ms; m < NTOK; m += 5) {
            const float4* k4 = (const float4*)&ks[m * HD];
            float dot = 0.0f;
            #pragma unroll
            for (int i = 0; i < 8; i++) {
                float4 kk = k4[i];
                dot += q[i].x * kk.x + q[i].y * kk.y + q[i].z * kk.z + q[i].w * kk.w;
            }
            int im = m / WS, jm = m - im * WS;
            int rel = (in_ - im + WS - 1) * (2 * WS - 1) + (jn - jm + WS - 1);
            dot += rpb[rel * NHD + head];
            int hm = wi * WS + im, wm = wj * WS + jm;
            int vm = (hm < HH - WS ? 0 : (hm < HH - SHIFT ? 1 : 2)) * 3
                   + (wm < WW - WS ? 0 : (wm < WW - SHIFT ? 1 : 2));
            if (vn != vm) dot -= 100.0f;
            S[n * 52 + m] = dot;
        }
    }
    __syncthreads();

    int warp = tid >> 5, lane = tid & 31;
    for (int n = warp; n < NTOK; n += 8) {
        float mx = -1e30f;
        for (int m = lane; m < NTOK; m += 32) mx = fmaxf(mx, S[n * 52 + m]);
        #pragma unroll
        for (int o = 16; o; o >>= 1) mx = fmaxf(mx, __shfl_xor_sync(0xffffffffu, mx, o));
        float sum = 0.0f;
        for (int m = lane; m < NTOK; m += 32) {
            float e = __expf(S[n * 52 + m] - mx);
            S[n * 52 + m] = e;
            sum += e;
        }
        #pragma unroll
        for (int o = 16; o; o >>= 1) sum += __shfl_xor_sync(0xffffffffu, sum, o);
        float inv = 1.0f / sum;
        for (int m = lane; m < NTOK; m += 32) S[n * 52 + m] *= inv;
    }
    __syncthreads();

    const float4* v4 = (const float4*)vs;
    for (int idx = tid; idx < NTOK * 8; idx += 256) {
        int n = idx >> 3, dq = idx & 7;
        float4 s4 = make_float4(0.f, 0.f, 0.f, 0.f);
        for (int m = 0; m < NTOK; m++) {
            float p = S[n * 52 + m];
            float4 v = v4[m * 8 + dq];
            s4.x += p * v.x; s4.y += p * v.y; s4.z += p * v.z; s4.w += p * v.w;
        }
        __half2* orow = (__half2*)(ow + ((size_t)win * NTOK + n) * CC + head * HD + dq * 4);
        orow[0] = __floats2half2_rn(s4.x, s4.y);
        orow[1] = __floats2half2_rn(s4.z, s4.w);
    }
}

// ---------------- launch ----------------
extern "C" void kernel_launch(void* const* d_in, const int* in_sizes, int n_in,
                              void* d_out, int out_size)
{
    const float* x      = (const float*)d_in[0];
    const float* qkv_w  = (const float*)d_in[1];
    const float* qkv_b  = (const float*)d_in[2];
    const float* proj_w = (const float*)d_in[3];
    const float* proj_b = (const float*)d_in[4];
    const float* rpb    = (const float*)d_in[5];
    const float* n1g    = (const float*)d_in[6];
    const float* n1b    = (const float*)d_in[7];
    const float* n2g    = (const float*)d_in[8];
    const float* n2b    = (const float*)d_in[9];
    const float* fc1_w  = (const float*)d_in[10];
    const float* fc1_b  = (const float*)d_in[11];
    const float* fc2_w  = (const float*)d_in[12];
    const float* fc2_b  = (const float*)d_in[13];
    float* out = (float*)d_out;

    __half *xw, *ow, *ln2, *mid, *wh_qkv, *wh_proj, *wh_fc1, *wh_fc2;
    float *qkv, *y; int* dmap;
    cudaGetSymbolAddress((void**)&xw,      g_xw);
    cudaGetSymbolAddress((void**)&qkv,     g_qkv);
    cudaGetSymbolAddress((void**)&ow,      g_ow);
    cudaGetSymbolAddress((void**)&y,       g_y);
    cudaGetSymbolAddress((void**)&ln2,     g_ln2);
    cudaGetSymbolAddress((void**)&mid,     g_mid);
    cudaGetSymbolAddress((void**)&dmap,    g_dmap);
    cudaGetSymbolAddress((void**)&wh_qkv,  g_wh_qkv);
    cudaGetSymbolAddress((void**)&wh_proj, g_wh_proj);
    cudaGetSymbolAddress((void**)&wh_fc1,  g_wh_fc1);
    cudaGetSymbolAddress((void**)&wh_fc2,  g_wh_fc2);

    cudaFuncSetAttribute(mma_gemm, cudaFuncAttributeMaxDynamicSharedMemorySize, SMEM_BYTES);

    // 0. convert + transpose weights to fp16 [N][K]
    convw_kernel<<<dim3((3 * CC) / 32, CC / 32), dim3(32, 8)>>>(qkv_w, wh_qkv, CC, 3 * CC);
    convw_kernel<<<dim3(CC / 32, CC / 32),       dim3(32, 8)>>>(proj_w, wh_proj, CC, CC);
    convw_kernel<<<dim3(HID / 32, CC / 32),      dim3(32, 8)>>>(fc1_w, wh_fc1, CC, HID);
    convw_kernel<<<dim3(CC / 32, HID / 32),      dim3(32, 8)>>>(fc2_w, wh_fc2, HID, CC);

    // 1. LN1 + shift + window partition (fp16 out)
    ln_kernel<<<TOK, 96>>>(x, n1g, n1b, xw, 1);

    // 2. QKV: (50176,384) @ (384,1152) -> fp32
    mma_gemm<<<dim3((3 * CC) / 128, TOK / 128), 256, SMEM_BYTES>>>(
        xw, wh_qkv, qkv_b, qkv, nullptr, nullptr, nullptr, TOK, 3 * CC, CC, 0);

    // 3. Windowed attention -> fp16
    attn_kernel<<<dim3(NHD, NWINS), 256>>>(rpb, ow);

    // 4. Proj + window reverse + residual -> fp32 y
    mma_gemm<<<dim3(CC / 128, TOK / 128), 256, SMEM_BYTES>>>(
        ow, wh_proj, proj_b, y, nullptr, x, dmap, TOK, CC, CC, 0);

    // 5. LN2 (fp16 out)
    ln_kernel<<<TOK, 96>>>(y, n2g, n2b, ln2, 0);

    // 6. FC1 + GELU -> fp16 mid
    mma_gemm<<<dim3(HID / 128, TOK / 128), 256, SMEM_BYTES>>>(
        ln2, wh_fc1, fc1_b, nullptr, mid, nullptr, nullptr, TOK, HID, CC, 1);

    // 7. FC2 + residual -> fp32 out
    mma_gemm<<<dim3(CC / 128, TOK / 128), 256, SMEM_BYTES>>>(
        mid, wh_fc2, fc2_b, out, nullptr, y, nullptr, TOK, CC, HID, 0);
}

// round 9
// speedup vs baseline: 1.4558x; 1.0685x over previous
#include <cuda_runtime.h>
#include <cuda_fp16.h>
#include <math.h>
#include <stdint.h>

// ---------------- problem constants ----------------
#define BB    64
#define HH    28
#define WW    28
#define CC    384
#define WS    7
#define SHIFT 3
#define NHD   12
#define HD    32
#define HID   1536
#define NWIN  16
#define NTOK  49
#define TOK   50176
#define NWINS 1024
#define ATT_SCALE 0.17677669529663687f

// ---------------- static scratch ----------------
__device__ __half g_xw  [(size_t)TOK * CC];       // LN1 out (fp16)
__device__ __half g_qkvh[(size_t)TOK * 3 * CC];   // QKV out (fp16)
__device__ __half g_ow  [(size_t)TOK * CC];       // attention out (fp16)
__device__ float  g_y   [(size_t)TOK * CC];       // post-attn residual (fp32)
__device__ __half g_ln2 [(size_t)TOK * CC];       // LN2 out (fp16)
__device__ __half g_mid [(size_t)TOK * HID];      // FC1+GELU out (fp16)
__device__ int    g_dmap[TOK];
// fp16 transposed weights [N][K]
__device__ __half g_wh_qkv [(size_t)(3 * CC) * CC];
__device__ __half g_wh_proj[(size_t)CC * CC];
__device__ __half g_wh_fc1 [(size_t)HID * CC];
__device__ __half g_wh_fc2 [(size_t)CC * HID];

// ---------------- weight convert + transpose: fp32 [K][N] -> fp16 [N][K] ----------------
__global__ __launch_bounds__(256) void convw_kernel(
    const float* __restrict__ in, __half* __restrict__ out, int K, int N)
{
    __shared__ float t[32][33];
    int bx = blockIdx.x * 32, by = blockIdx.y * 32;
    int tx = threadIdx.x, ty = threadIdx.y;
    #pragma unroll
    for (int i = 0; i < 32; i += 8)
        t[ty + i][tx] = in[(size_t)(by + ty + i) * N + bx + tx];
    __syncthreads();
    #pragma unroll
    for (int i = 0; i < 32; i += 8)
        out[(size_t)(bx + ty + i) * K + by + tx] = __float2half_rn(t[tx][ty + i]);
}

// ---------------- LayerNorm -> fp16 (mode 1 fuses shift + window gather) ----------------
__global__ __launch_bounds__(96) void ln_kernel(
    const float* __restrict__ x, const float* __restrict__ g,
    const float* __restrict__ b, __half* __restrict__ out, int mode)
{
    int r = blockIdx.x;
    int src = r;
    if (mode == 1) {
        int win  = r / NTOK;
        int n    = r - win * NTOK;
        int bidx = win >> 4;
        int widx = win & 15;
        int wi = widx >> 2, wj = widx & 3;
        int ph = n / WS, pw = n - ph * WS;
        int h = (wi * WS + ph + SHIFT) % HH;
        int w = (wj * WS + pw + SHIFT) % WW;
        src = bidx * (HH * WW) + h * WW + w;
        if (threadIdx.x == 0) g_dmap[r] = src;
    }
    int t = threadIdx.x;
    const float4* xr = (const float4*)(x + (size_t)src * CC);
    float4 v = xr[t];
    float s  = v.x + v.y + v.z + v.w;
    float s2 = v.x * v.x + v.y * v.y + v.z * v.z + v.w * v.w;
    #pragma unroll
    for (int o = 16; o; o >>= 1) {
        s  += __shfl_xor_sync(0xffffffffu, s,  o);
        s2 += __shfl_xor_sync(0xffffffffu, s2, o);
    }
    __shared__ float sh[3], sh2[3];
    int warp = t >> 5, lane = t & 31;
    if (lane == 0) { sh[warp] = s; sh2[warp] = s2; }
    __syncthreads();
    if (t == 0) {
        float S  = sh[0] + sh[1] + sh[2];
        float S2 = sh2[0] + sh2[1] + sh2[2];
        float mu  = S * (1.0f / CC);
        float var = S2 * (1.0f / CC) - mu * mu;
        sh[0]  = mu;
        sh2[0] = rsqrtf(var + 1e-5f);
    }
    __syncthreads();
    float mu = sh[0], inv = sh2[0];
    float4 gg = ((const float4*)g)[t];
    float4 bb = ((const float4*)b)[t];
    float4 o4;
    o4.x = (v.x - mu) * inv * gg.x + bb.x;
    o4.y = (v.y - mu) * inv * gg.y + bb.y;
    o4.z = (v.z - mu) * inv * gg.z + bb.z;
    o4.w = (v.w - mu) * inv * gg.w + bb.w;
    __half2* orow = (__half2*)(out + (size_t)r * CC);
    orow[2 * t]     = __floats2half2_rn(o4.x, o4.y);
    orow[2 * t + 1] = __floats2half2_rn(o4.z, o4.w);
}

// ---------------- fp16 tensor-core GEMM (m16n8k16) + ldmatrix, 4-stage cp.async ----------------
// 128x128 CTA tile, GBK=32 halves, 8 warps 2m x 4n, warp tile 64x32.
// A:[M,K] fp16 row-major, Bt:[N,K] fp16 row-major. Smem rows = 32 halves padded
// to 40 (20 words): (5r+c) mod 8 bijective in r -> LDSM column reads conflict-free.
#define KC 32
#define WSTR 20                          // words per smem row
#define OP_W (128 * WSTR)
#define STG_W (2 * OP_W)
#define STAGES 4
#define SMEM_BYTES (STAGES * STG_W * 4)  // 81920

__device__ __forceinline__ void cp16(uint32_t s, const void* g) {
    asm volatile("cp.async.cg.shared.global [%0], [%1], 16;" :: "r"(s), "l"(g));
}

__global__ __launch_bounds__(256, 2) void mma_gemm(
    const __half* __restrict__ A, const __half* __restrict__ Bt,
    const float* __restrict__ bias, float* __restrict__ Cf,
    __half* __restrict__ Ch,
    const float* __restrict__ addend, const int* __restrict__ rowmap,
    int M, int Nn, int K, int act)
{
    extern __shared__ uint32_t sw[];
    uint32_t base = (uint32_t)__cvta_generic_to_shared(sw);

    int tid  = threadIdx.x;
    int warp = tid >> 5, lane = tid & 31;
    int g    = lane >> 2, t4 = lane & 3;
    int wm   = warp >> 2, wn = warp & 3;
    int tile_m = blockIdx.y * 128;
    int tile_n = blockIdx.x * 128;
    int nk = K / KC;

    // cp.async coords
    int rr[2], ch[2];
    #pragma unroll
    for (int i = 0; i < 2; i++) {
        int c = tid + i * 256;
        rr[i] = c >> 2;  ch[i] = c & 3;
    }

    auto issue = [&](int tile) {
        int k0 = tile * KC;
        int s  = tile & (STAGES - 1);
        uint32_t sb = base + (uint32_t)(s * STG_W) * 4u;
        #pragma unroll
        for (int i = 0; i < 2; i++)
            cp16(sb + (uint32_t)(rr[i] * WSTR + ch[i] * 4) * 4u,
                 &A[(size_t)(tile_m + rr[i]) * K + k0 + ch[i] * 8]);
        #pragma unroll
        for (int i = 0; i < 2; i++)
            cp16(sb + (uint32_t)(OP_W + rr[i] * WSTR + ch[i] * 4) * 4u,
                 &Bt[(size_t)(tile_n + rr[i]) * K + k0 + ch[i] * 8]);
        asm volatile("cp.async.commit_group;");
    };

    // ldmatrix per-lane byte offsets (within a stage)
    uint32_t a_off[4];
    #pragma unroll
    for (int mt = 0; mt < 4; mt++)
        a_off[mt] = (uint32_t)(((wm * 64 + mt * 16 + (lane & 15)) * WSTR
                               + (lane >> 4) * 4) * 4);
    uint32_t b_off[4];
    #pragma unroll
    for (int nt = 0; nt < 4; nt++)
        b_off[nt] = (uint32_t)((OP_W + (wn * 32 + nt * 8 + (lane & 7)) * WSTR
                               + ((lane >> 3) & 1) * 4) * 4);

    float acc[4][4][4];
    #pragma unroll
    for (int i = 0; i < 4; i++)
        #pragma unroll
        for (int j = 0; j < 4; j++)
            #pragma unroll
            for (int q = 0; q < 4; q++) acc[i][j][q] = 0.0f;

    #pragma unroll
    for (int s = 0; s < STAGES - 1; s++) issue(s);

    for (int it = 0; it < nk; it++) {
        asm volatile("cp.async.wait_group %0;" :: "n"(STAGES - 2));
        __syncthreads();
        int s = it & (STAGES - 1);
        uint32_t sb = base + (uint32_t)(s * STG_W) * 4u;
        int nxt = it + STAGES - 1;
        if (nxt < nk) issue(nxt);
        else asm volatile("cp.async.commit_group;");

        #pragma unroll
        for (int ks = 0; ks < 2; ks++) {
            uint32_t kb = (uint32_t)(ks * 8 * 4);   // k16 block byte offset
            unsigned a[4][4], bfr[4][2];
            #pragma unroll
            for (int mt = 0; mt < 4; mt++)
                asm volatile(
                    "ldmatrix.sync.aligned.m8n8.x4.shared.b16 {%0,%1,%2,%3}, [%4];"
                    : "=r"(a[mt][0]), "=r"(a[mt][1]), "=r"(a[mt][2]), "=r"(a[mt][3])
                    : "r"(sb + a_off[mt] + kb));
            #pragma unroll
            for (int nt = 0; nt < 4; nt++)
                asm volatile(
                    "ldmatrix.sync.aligned.m8n8.x2.shared.b16 {%0,%1}, [%2];"
                    : "=r"(bfr[nt][0]), "=r"(bfr[nt][1])
                    : "r"(sb + b_off[nt] + kb));
            #pragma unroll
            for (int mt = 0; mt < 4; mt++)
                #pragma unroll
                for (int nt = 0; nt < 4; nt++) {
                    asm volatile(
                        "mma.sync.aligned.m16n8k16.row.col.f32.f16.f16.f32 "
                        "{%0,%1,%2,%3},{%4,%5,%6,%7},{%8,%9},{%0,%1,%2,%3};"
                        : "+f"(acc[mt][nt][0]), "+f"(acc[mt][nt][1]),
                          "+f"(acc[mt][nt][2]), "+f"(acc[mt][nt][3])
                        : "r"(a[mt][0]), "r"(a[mt][1]), "r"(a[mt][2]), "r"(a[mt][3]),
                          "r"(bfr[nt][0]), "r"(bfr[nt][1]));
                }
        }
    }

    // epilogue
    #pragma unroll
    for (int mt = 0; mt < 4; mt++) {
        int r0 = tile_m + wm * 64 + mt * 16 + g;
        int r1 = r0 + 8;
        int o0 = rowmap ? rowmap[r0] : r0;
        int o1 = rowmap ? rowmap[r1] : r1;
        #pragma unroll
        for (int nt = 0; nt < 4; nt++) {
            int c0 = tile_n + wn * 32 + nt * 8 + 2 * t4;
            float b0 = bias[c0], b1 = bias[c0 + 1];
            float v0 = acc[mt][nt][0] + b0, v1 = acc[mt][nt][1] + b1;
            float v2 = acc[mt][nt][2] + b0, v3 = acc[mt][nt][3] + b1;
            if (act == 1) {
                v0 = 0.5f * v0 * (1.0f + erff(v0 * 0.70710678118654752f));
                v1 = 0.5f * v1 * (1.0f + erff(v1 * 0.70710678118654752f));
                v2 = 0.5f * v2 * (1.0f + erff(v2 * 0.70710678118654752f));
                v3 = 0.5f * v3 * (1.0f + erff(v3 * 0.70710678118654752f));
            }
            size_t f0 = (size_t)o0 * Nn + c0;
            size_t f1 = (size_t)o1 * Nn + c0;
            if (addend) {
                v0 += addend[f0]; v1 += addend[f0 + 1];
                v2 += addend[f1]; v3 += addend[f1 + 1];
            }
            if (Ch) {
                *(__half2*)&Ch[f0] = __floats2half2_rn(v0, v1);
                *(__half2*)&Ch[f1] = __floats2half2_rn(v2, v3);
            } else {
                Cf[f0] = v0; Cf[f0 + 1] = v1;
                Cf[f1] = v2; Cf[f1 + 1] = v3;
            }
        }
    }
}

// ---------------- windowed attention (fp16 qkv in, fp16 out) ----------------
__global__ __launch_bounds__(256) void attn_kernel(
    const float* __restrict__ rpb, __half* __restrict__ ow)
{
    int head = blockIdx.x;
    int win  = blockIdx.y;
    __shared__ __align__(16) float qs[NTOK * HD];
    __shared__ __align__(16) float ks[NTOK * HD];
    __shared__ __align__(16) float vs[NTOK * HD];
    __shared__ float S[NTOK * 52];

    int tid = threadIdx.x;
    const __half* base = g_qkvh + (size_t)win * NTOK * (3 * CC) + head * HD;

    for (int idx = tid; idx < NTOK * 16; idx += 256) {
        int n = idx >> 4, d2 = idx & 15;
        const __half2* row = (const __half2*)(base + (size_t)n * (3 * CC));
        float2 q2 = __half22float2(row[d2]);
        float2 k2 = __half22float2(row[CC / 2 + d2]);
        float2 v2 = __half22float2(row[CC + d2]);
        qs[n * HD + 2 * d2]     = q2.x * ATT_SCALE;
        qs[n * HD + 2 * d2 + 1] = q2.y * ATT_SCALE;
        ks[n * HD + 2 * d2]     = k2.x;
        ks[n * HD + 2 * d2 + 1] = k2.y;
        vs[n * HD + 2 * d2]     = v2.x;
        vs[n * HD + 2 * d2 + 1] = v2.y;
    }
    __syncthreads();

    int widx = win & 15;
    int wi = widx >> 2, wj = widx & 3;

    if (tid < 245) {
        int n  = tid / 5;
        int ms = tid - n * 5;
        float4 q[8];
        const float4* q4 = (const float4*)&qs[n * HD];
        #pragma unroll
        for (int i = 0; i < 8; i++) q[i] = q4[i];

        int in_ = n / WS, jn = n - in_ * WS;
        int hn = wi * WS + in_, wn_ = wj * WS + jn;
        int vn = (hn < HH - WS ? 0 : (hn < HH - SHIFT ? 1 : 2)) * 3
               + (wn_ < WW - WS ? 0 : (wn_ < WW - SHIFT ? 1 : 2));

        for (int m = ms; m < NTOK; m += 5) {
            const float4* k4 = (const float4*)&ks[m * HD];
            float dot = 0.0f;
            #pragma unroll
            for (int i = 0; i < 8; i++) {
                float4 kk = k4[i];
                dot += q[i].x * kk.x + q[i].y * kk.y + q[i].z * kk.z + q[i].w * kk.w;
            }
            int im = m / WS, jm = m - im * WS;
            int rel = (in_ - im + WS - 1) * (2 * WS - 1) + (jn - jm + WS - 1);
            dot += rpb[rel * NHD + head];
            int hm = wi * WS + im, wm = wj * WS + jm;
            int vm = (hm < HH - WS ? 0 : (hm < HH - SHIFT ? 1 : 2)) * 3
                   + (wm < WW - WS ? 0 : (wm < WW - SHIFT ? 1 : 2));
            if (vn != vm) dot -= 100.0f;
            S[n * 52 + m] = dot;
        }
    }
    __syncthreads();

    int warp = tid >> 5, lane = tid & 31;
    for (int n = warp; n < NTOK; n += 8) {
        float mx = -1e30f;
        for (int m = lane; m < NTOK; m += 32) mx = fmaxf(mx, S[n * 52 + m]);
        #pragma unroll
        for (int o = 16; o; o >>= 1) mx = fmaxf(mx, __shfl_xor_sync(0xffffffffu, mx, o));
        float sum = 0.0f;
        for (int m = lane; m < NTOK; m += 32) {
            float e = __expf(S[n * 52 + m] - mx);
            S[n * 52 + m] = e;
            sum += e;
        }
        #pragma unroll
        for (int o = 16; o; o >>= 1) sum += __shfl_xor_sync(0xffffffffu, sum, o);
        float inv = 1.0f / sum;
        for (int m = lane; m < NTOK; m += 32) S[n * 52 + m] *= inv;
    }
    __syncthreads();

    const float4* v4 = (const float4*)vs;
    for (int idx = tid; idx < NTOK * 8; idx += 256) {
        int n = idx >> 3, dq = idx & 7;
        float4 s4 = make_float4(0.f, 0.f, 0.f, 0.f);
        for (int m = 0; m < NTOK; m++) {
            float p = S[n * 52 + m];
            float4 v = v4[m * 8 + dq];
            s4.x += p * v.x; s4.y += p * v.y; s4.z += p * v.z; s4.w += p * v.w;
        }
        __half2* orow = (__half2*)(ow + ((size_t)win * NTOK + n) * CC + head * HD + dq * 4);
        orow[0] = __floats2half2_rn(s4.x, s4.y);
        orow[1] = __floats2half2_rn(s4.z, s4.w);
    }
}

// ---------------- launch ----------------
extern "C" void kernel_launch(void* const* d_in, const int* in_sizes, int n_in,
                              void* d_out, int out_size)
{
    const float* x      = (const float*)d_in[0];
    const float* qkv_w  = (const float*)d_in[1];
    const float* qkv_b  = (const float*)d_in[2];
    const float* proj_w = (const float*)d_in[3];
    const float* proj_b = (const float*)d_in[4];
    const float* rpb    = (const float*)d_in[5];
    const float* n1g    = (const float*)d_in[6];
    const float* n1b    = (const float*)d_in[7];
    const float* n2g    = (const float*)d_in[8];
    const float* n2b    = (const float*)d_in[9];
    const float* fc1_w  = (const float*)d_in[10];
    const float* fc1_b  = (const float*)d_in[11];
    const float* fc2_w  = (const float*)d_in[12];
    const float* fc2_b  = (const float*)d_in[13];
    float* out = (float*)d_out;

    __half *xw, *qkvh, *ow, *ln2, *mid, *wh_qkv, *wh_proj, *wh_fc1, *wh_fc2;
    float *y; int* dmap;
    cudaGetSymbolAddress((void**)&xw,      g_xw);
    cudaGetSymbolAddress((void**)&qkvh,    g_qkvh);
    cudaGetSymbolAddress((void**)&ow,      g_ow);
    cudaGetSymbolAddress((void**)&y,       g_y);
    cudaGetSymbolAddress((void**)&ln2,     g_ln2);
    cudaGetSymbolAddress((void**)&mid,     g_mid);
    cudaGetSymbolAddress((void**)&dmap,    g_dmap);
    cudaGetSymbolAddress((void**)&wh_qkv,  g_wh_qkv);
    cudaGetSymbolAddress((void**)&wh_proj, g_wh_proj);
    cudaGetSymbolAddress((void**)&wh_fc1,  g_wh_fc1);
    cudaGetSymbolAddress((void**)&wh_fc2,  g_wh_fc2);

    cudaFuncSetAttribute(mma_gemm, cudaFuncAttributeMaxDynamicSharedMemorySize, SMEM_BYTES);

    // 0. convert + transpose weights to fp16 [N][K]
    convw_kernel<<<dim3((3 * CC) / 32, CC / 32), dim3(32, 8)>>>(qkv_w, wh_qkv, CC, 3 * CC);
    convw_kernel<<<dim3(CC / 32, CC / 32),       dim3(32, 8)>>>(proj_w, wh_proj, CC, CC);
    convw_kernel<<<dim3(HID / 32, CC / 32),      dim3(32, 8)>>>(fc1_w, wh_fc1, CC, HID);
    convw_kernel<<<dim3(CC / 32, HID / 32),      dim3(32, 8)>>>(fc2_w, wh_fc2, HID, CC);

    // 1. LN1 + shift + window partition (fp16 out)
    ln_kernel<<<TOK, 96>>>(x, n1g, n1b, xw, 1);

    // 2. QKV -> fp16
    mma_gemm<<<dim3((3 * CC) / 128, TOK / 128), 256, SMEM_BYTES>>>(
        xw, wh_qkv, qkv_b, nullptr, qkvh, nullptr, nullptr, TOK, 3 * CC, CC, 0);

    // 3. Windowed attention -> fp16
    attn_kernel<<<dim3(NHD, NWINS), 256>>>(rpb, ow);

    // 4. Proj + window reverse + residual -> fp32 y
    mma_gemm<<<dim3(CC / 128, TOK / 128), 256, SMEM_BYTES>>>(
        ow, wh_proj, proj_b, y, nullptr, x, dmap, TOK, CC, CC, 0);

    // 5. LN2 (fp16 out)
    ln_kernel<<<TOK, 96>>>(y, n2g, n2b, ln2, 0);

    // 6. FC1 + GELU -> fp16 mid
    mma_gemm<<<dim3(HID / 128, TOK / 128), 256, SMEM_BYTES>>>(
        ln2, wh_fc1, fc1_b, nullptr, mid, nullptr, nullptr, TOK, HID, CC, 1);

    // 7. FC2 + residual -> fp32 out
    mma_gemm<<<dim3(CC / 128, TOK / 128), 256, SMEM_BYTES>>>(
        mid, wh_fc2, fc2_b, out, nullptr, y, nullptr, TOK, CC, HID, 0);
}

// round 10
// speedup vs baseline: 2.3880x; 1.6403x over previous
#include <cuda_runtime.h>
#include <cuda_fp16.h>
#include <math.h>
#include <stdint.h>

// ---------------- problem constants ----------------
#define BB    64
#define HH    28
#define WW    28
#define CC    384
#define WS    7
#define SHIFT 3
#define NHD   12
#define HD    32
#define HID   1536
#define NWIN  16
#define NTOK  49
#define TOK   50176
#define NWINS 1024
#define ATT_SCALE 0.17677669529663687f

// ---------------- static scratch ----------------
__device__ __half g_xw  [(size_t)TOK * CC];
__device__ __half g_qkvh[(size_t)TOK * 3 * CC];
__device__ __half g_ow  [(size_t)TOK * CC];
__device__ float  g_y   [(size_t)TOK * CC];
__device__ __half g_ln2 [(size_t)TOK * CC];
__device__ __half g_mid [(size_t)TOK * HID];
__device__ int    g_dmap[TOK];
__device__ float  g_bm  [(size_t)NHD * 16 * NTOK * 56];   // bias+mask table
// fp16 transposed weights [N][K]
__device__ __half g_wh_qkv [(size_t)(3 * CC) * CC];
__device__ __half g_wh_proj[(size_t)CC * CC];
__device__ __half g_wh_fc1 [(size_t)HID * CC];
__device__ __half g_wh_fc2 [(size_t)CC * HID];

// ---------------- weight convert + transpose: fp32 [K][N] -> fp16 [N][K] ----------------
__global__ __launch_bounds__(256) void convw_kernel(
    const float* __restrict__ in, __half* __restrict__ out, int K, int N)
{
    __shared__ float t[32][33];
    int bx = blockIdx.x * 32, by = blockIdx.y * 32;
    int tx = threadIdx.x, ty = threadIdx.y;
    #pragma unroll
    for (int i = 0; i < 32; i += 8)
        t[ty + i][tx] = in[(size_t)(by + ty + i) * N + bx + tx];
    __syncthreads();
    #pragma unroll
    for (int i = 0; i < 32; i += 8)
        out[(size_t)(bx + ty + i) * K + by + tx] = __float2half_rn(t[tx][ty + i]);
}

// ---------------- bias + shift-mask precompute: bm[head][wm][n][m'] ----------------
__global__ __launch_bounds__(256) void bm_kernel(
    const float* __restrict__ rpb, float* __restrict__ bm)
{
    int wm   = blockIdx.x;   // 0..15
    int head = blockIdx.y;   // 0..11
    int wi = wm >> 2, wj = wm & 3;
    for (int idx = threadIdx.x; idx < NTOK * 56; idx += 256) {
        int n = idx / 56, m = idx - n * 56;
        float val;
        if (m >= NTOK) {
            val = -30000.0f;
        } else {
            int in_ = n / WS, jn = n % WS, im = m / WS, jm = m % WS;
            int rel = (in_ - im + WS - 1) * (2 * WS - 1) + (jn - jm + WS - 1);
            val = rpb[rel * NHD + head];
            int hn = wi * WS + in_, wn = wj * WS + jn;
            int hm = wi * WS + im, wmm = wj * WS + jm;
            int vn = (hn < HH - WS ? 0 : (hn < HH - SHIFT ? 1 : 2)) * 3
                   + (wn < WW - WS ? 0 : (wn < WW - SHIFT ? 1 : 2));
            int vm = (hm < HH - WS ? 0 : (hm < HH - SHIFT ? 1 : 2)) * 3
                   + (wmm < WW - WS ? 0 : (wmm < WW - SHIFT ? 1 : 2));
            if (vn != vm) val -= 100.0f;
        }
        bm[((size_t)(head * 16 + wm) * NTOK + n) * 56 + m] = val;
    }
}

// ---------------- LayerNorm -> fp16 (mode 1 fuses shift + window gather) ----------------
__global__ __launch_bounds__(96) void ln_kernel(
    const float* __restrict__ x, const float* __restrict__ g,
    const float* __restrict__ b, __half* __restrict__ out, int mode)
{
    int r = blockIdx.x;
    int src = r;
    if (mode == 1) {
        int win  = r / NTOK;
        int n    = r - win * NTOK;
        int bidx = win >> 4;
        int widx = win & 15;
        int wi = widx >> 2, wj = widx & 3;
        int ph = n / WS, pw = n - ph * WS;
        int h = (wi * WS + ph + SHIFT) % HH;
        int w = (wj * WS + pw + SHIFT) % WW;
        src = bidx * (HH * WW) + h * WW + w;
        if (threadIdx.x == 0) g_dmap[r] = src;
    }
    int t = threadIdx.x;
    const float4* xr = (const float4*)(x + (size_t)src * CC);
    float4 v = xr[t];
    float s  = v.x + v.y + v.z + v.w;
    float s2 = v.x * v.x + v.y * v.y + v.z * v.z + v.w * v.w;
    #pragma unroll
    for (int o = 16; o; o >>= 1) {
        s  += __shfl_xor_sync(0xffffffffu, s,  o);
        s2 += __shfl_xor_sync(0xffffffffu, s2, o);
    }
    __shared__ float sh[3], sh2[3];
    int warp = t >> 5, lane = t & 31;
    if (lane == 0) { sh[warp] = s; sh2[warp] = s2; }
    __syncthreads();
    if (t == 0) {
        float S  = sh[0] + sh[1] + sh[2];
        float S2 = sh2[0] + sh2[1] + sh2[2];
        float mu  = S * (1.0f / CC);
        float var = S2 * (1.0f / CC) - mu * mu;
        sh[0]  = mu;
        sh2[0] = rsqrtf(var + 1e-5f);
    }
    __syncthreads();
    float mu = sh[0], inv = sh2[0];
    float4 gg = ((const float4*)g)[t];
    float4 bb = ((const float4*)b)[t];
    float4 o4;
    o4.x = (v.x - mu) * inv * gg.x + bb.x;
    o4.y = (v.y - mu) * inv * gg.y + bb.y;
    o4.z = (v.z - mu) * inv * gg.z + bb.z;
    o4.w = (v.w - mu) * inv * gg.w + bb.w;
    __half2* orow = (__half2*)(out + (size_t)r * CC);
    orow[2 * t]     = __floats2half2_rn(o4.x, o4.y);
    orow[2 * t + 1] = __floats2half2_rn(o4.z, o4.w);
}

// ---------------- fp16 tensor-core GEMM (m16n8k16) + ldmatrix, 4-stage cp.async ----------------
#define KC 32
#define WSTR 20
#define OP_W (128 * WSTR)
#define STG_W (2 * OP_W)
#define STAGES 4
#define SMEM_BYTES (STAGES * STG_W * 4)

__device__ __forceinline__ void cp16(uint32_t s, const void* g) {
    asm volatile("cp.async.cg.shared.global [%0], [%1], 16;" :: "r"(s), "l"(g));
}

__global__ __launch_bounds__(256, 2) void mma_gemm(
    const __half* __restrict__ A, const __half* __restrict__ Bt,
    const float* __restrict__ bias, float* __restrict__ Cf,
    __half* __restrict__ Ch,
    const float* __restrict__ addend, const int* __restrict__ rowmap,
    int M, int Nn, int K, int act)
{
    extern __shared__ uint32_t sw[];
    uint32_t base = (uint32_t)__cvta_generic_to_shared(sw);

    int tid  = threadIdx.x;
    int warp = tid >> 5, lane = tid & 31;
    int g    = lane >> 2, t4 = lane & 3;
    int wm   = warp >> 2, wn = warp & 3;
    int tile_m = blockIdx.y * 128;
    int tile_n = blockIdx.x * 128;
    int nk = K / KC;

    int rr[2], ch[2];
    #pragma unroll
    for (int i = 0; i < 2; i++) {
        int c = tid + i * 256;
        rr[i] = c >> 2;  ch[i] = c & 3;
    }

    auto issue = [&](int tile) {
        int k0 = tile * KC;
        int s  = tile & (STAGES - 1);
        uint32_t sb = base + (uint32_t)(s * STG_W) * 4u;
        #pragma unroll
        for (int i = 0; i < 2; i++)
            cp16(sb + (uint32_t)(rr[i] * WSTR + ch[i] * 4) * 4u,
                 &A[(size_t)(tile_m + rr[i]) * K + k0 + ch[i] * 8]);
        #pragma unroll
        for (int i = 0; i < 2; i++)
            cp16(sb + (uint32_t)(OP_W + rr[i] * WSTR + ch[i] * 4) * 4u,
                 &Bt[(size_t)(tile_n + rr[i]) * K + k0 + ch[i] * 8]);
        asm volatile("cp.async.commit_group;");
    };

    uint32_t a_off[4];
    #pragma unroll
    for (int mt = 0; mt < 4; mt++)
        a_off[mt] = (uint32_t)(((wm * 64 + mt * 16 + (lane & 15)) * WSTR
                               + (lane >> 4) * 4) * 4);
    uint32_t b_off[4];
    #pragma unroll
    for (int nt = 0; nt < 4; nt++)
        b_off[nt] = (uint32_t)((OP_W + (wn * 32 + nt * 8 + (lane & 7)) * WSTR
                               + ((lane >> 3) & 1) * 4) * 4);

    float acc[4][4][4];
    #pragma unroll
    for (int i = 0; i < 4; i++)
        #pragma unroll
        for (int j = 0; j < 4; j++)
            #pragma unroll
            for (int q = 0; q < 4; q++) acc[i][j][q] = 0.0f;

    #pragma unroll
    for (int s = 0; s < STAGES - 1; s++) issue(s);

    for (int it = 0; it < nk; it++) {
        asm volatile("cp.async.wait_group %0;" :: "n"(STAGES - 2));
        __syncthreads();
        int s = it & (STAGES - 1);
        uint32_t sb = base + (uint32_t)(s * STG_W) * 4u;
        int nxt = it + STAGES - 1;
        if (nxt < nk) issue(nxt);
        else asm volatile("cp.async.commit_group;");

        #pragma unroll
        for (int ks = 0; ks < 2; ks++) {
            uint32_t kb = (uint32_t)(ks * 8 * 4);
            unsigned a[4][4], bfr[4][2];
            #pragma unroll
            for (int mt = 0; mt < 4; mt++)
                asm volatile(
                    "ldmatrix.sync.aligned.m8n8.x4.shared.b16 {%0,%1,%2,%3}, [%4];"
                    : "=r"(a[mt][0]), "=r"(a[mt][1]), "=r"(a[mt][2]), "=r"(a[mt][3])
                    : "r"(sb + a_off[mt] + kb));
            #pragma unroll
            for (int nt = 0; nt < 4; nt++)
                asm volatile(
                    "ldmatrix.sync.aligned.m8n8.x2.shared.b16 {%0,%1}, [%2];"
                    : "=r"(bfr[nt][0]), "=r"(bfr[nt][1])
                    : "r"(sb + b_off[nt] + kb));
            #pragma unroll
            for (int mt = 0; mt < 4; mt++)
                #pragma unroll
                for (int nt = 0; nt < 4; nt++) {
                    asm volatile(
                        "mma.sync.aligned.m16n8k16.row.col.f32.f16.f16.f32 "
                        "{%0,%1,%2,%3},{%4,%5,%6,%7},{%8,%9},{%0,%1,%2,%3};"
                        : "+f"(acc[mt][nt][0]), "+f"(acc[mt][nt][1]),
                          "+f"(acc[mt][nt][2]), "+f"(acc[mt][nt][3])
                        : "r"(a[mt][0]), "r"(a[mt][1]), "r"(a[mt][2]), "r"(a[mt][3]),
                          "r"(bfr[nt][0]), "r"(bfr[nt][1]));
                }
        }
    }

    #pragma unroll
    for (int mt = 0; mt < 4; mt++) {
        int r0 = tile_m + wm * 64 + mt * 16 + g;
        int r1 = r0 + 8;
        int o0 = rowmap ? rowmap[r0] : r0;
        int o1 = rowmap ? rowmap[r1] : r1;
        #pragma unroll
        for (int nt = 0; nt < 4; nt++) {
            int c0 = tile_n + wn * 32 + nt * 8 + 2 * t4;
            float b0 = bias[c0], b1 = bias[c0 + 1];
            float v0 = acc[mt][nt][0] + b0, v1 = acc[mt][nt][1] + b1;
            float v2 = acc[mt][nt][2] + b0, v3 = acc[mt][nt][3] + b1;
            if (act == 1) {
                v0 = 0.5f * v0 * (1.0f + erff(v0 * 0.70710678118654752f));
                v1 = 0.5f * v1 * (1.0f + erff(v1 * 0.70710678118654752f));
                v2 = 0.5f * v2 * (1.0f + erff(v2 * 0.70710678118654752f));
                v3 = 0.5f * v3 * (1.0f + erff(v3 * 0.70710678118654752f));
            }
            size_t f0 = (size_t)o0 * Nn + c0;
            size_t f1 = (size_t)o1 * Nn + c0;
            if (addend) {
                v0 += addend[f0]; v1 += addend[f0 + 1];
                v2 += addend[f1]; v3 += addend[f1 + 1];
            }
            if (Ch) {
                *(__half2*)&Ch[f0] = __floats2half2_rn(v0, v1);
                *(__half2*)&Ch[f1] = __floats2half2_rn(v2, v3);
            } else {
                Cf[f0] = v0; Cf[f0 + 1] = v1;
                Cf[f1] = v2; Cf[f1 + 1] = v3;
            }
        }
    }
}

// ---------------- mma windowed attention: 1 warp = 1 (window, head) ----------------
// smem per warp (halves): Q 64x40 @0, K 56x40 @2560, Vt 32x72 @4800. Total 7168.
#define AW_H   7168
#define AQ_OFF 0
#define AK_OFF 2560
#define AV_OFF 4800
#define ATT_SMEM (4 * AW_H * 2)   // 57344 bytes

__global__ __launch_bounds__(128) void attn_mma_kernel(
    const float* __restrict__ bm, __half* __restrict__ ow)
{
    extern __shared__ __half ash[];
    int tid  = threadIdx.x;
    int warp = tid >> 5, lane = tid & 31;
    int unit = blockIdx.x * 4 + warp;
    int head = unit >> 10;       // 0..11
    int win  = unit & 1023;      // 0..1023
    int g = lane >> 2, t4 = lane & 3;

    __half* ws = ash + warp * AW_H;
    uint32_t wsu = (uint32_t)__cvta_generic_to_shared(ws);

    // zero warp region (covers all pads)
    {
        uint4 zz = make_uint4(0, 0, 0, 0);
        uint4* p = (uint4*)ws;
        #pragma unroll
        for (int i = 0; i < AW_H / 8 / 32; i++)
            p[lane + i * 32] = zz;
    }
    __syncwarp();

    // load Q, K (49 rows x 32 halves; 4 16B chunks/row)
    const __half* qb = g_qkvh + (size_t)win * NTOK * (3 * CC) + head * HD;
    for (int c = lane; c < NTOK * 4; c += 32) {
        int row = c >> 2, cq = c & 3;
        const __half* src = qb + (size_t)row * (3 * CC) + cq * 8;
        *(uint4*)(ws + AQ_OFF + row * 40 + cq * 8) = *(const uint4*)(src);
        *(uint4*)(ws + AK_OFF + row * 40 + cq * 8) = *(const uint4*)(src + CC);
    }
    // load V transposed: Vt[d][m], row stride 72 halves
    for (int c = lane; c < NTOK * 16; c += 32) {
        int m = c >> 4, d2 = c & 15;
        __half2 v = *(const __half2*)(qb + (size_t)m * (3 * CC) + 2 * CC + d2 * 2);
        ws[AV_OFF + (2 * d2)     * 72 + m] = __low2half(v);
        ws[AV_OFF + (2 * d2 + 1) * 72 + m] = __high2half(v);
    }
    __syncwarp();

    // ldmatrix base addresses (bytes)
    uint32_t qa[4], kf[7], vf[4];
    #pragma unroll
    for (int mt = 0; mt < 4; mt++)
        qa[mt] = wsu + (uint32_t)((AQ_OFF + (mt * 16 + (lane & 15)) * 40
                                   + (lane >> 4) * 8) * 2);
    #pragma unroll
    for (int nt = 0; nt < 7; nt++)
        kf[nt] = wsu + (uint32_t)((AK_OFF + (nt * 8 + (lane & 7)) * 40
                                   + ((lane >> 3) & 1) * 8) * 2);
    #pragma unroll
    for (int nt = 0; nt < 4; nt++)
        vf[nt] = wsu + (uint32_t)((AV_OFF + (nt * 8 + (lane & 7)) * 72
                                   + ((lane >> 3) & 1) * 8) * 2);

    // S = Q @ K^T  (fp32 accum)
    float sa[4][7][4];
    #pragma unroll
    for (int i = 0; i < 4; i++)
        #pragma unroll
        for (int j = 0; j < 7; j++)
            #pragma unroll
            for (int q = 0; q < 4; q++) sa[i][j][q] = 0.0f;

    #pragma unroll
    for (int ks = 0; ks < 2; ks++) {
        uint32_t kb = (uint32_t)(ks * 32);   // 16 halves
        unsigned a[4][4], b[7][2];
        #pragma unroll
        for (int mt = 0; mt < 4; mt++)
            asm volatile(
                "ldmatrix.sync.aligned.m8n8.x4.shared.b16 {%0,%1,%2,%3}, [%4];"
                : "=r"(a[mt][0]), "=r"(a[mt][1]), "=r"(a[mt][2]), "=r"(a[mt][3])
                : "r"(qa[mt] + kb));
        #pragma unroll
        for (int nt = 0; nt < 7; nt++)
            asm volatile(
                "ldmatrix.sync.aligned.m8n8.x2.shared.b16 {%0,%1}, [%2];"
                : "=r"(b[nt][0]), "=r"(b[nt][1]) : "r"(kf[nt] + kb));
        #pragma unroll
        for (int mt = 0; mt < 4; mt++)
            #pragma unroll
            for (int nt = 0; nt < 7; nt++)
                asm volatile(
                    "mma.sync.aligned.m16n8k16.row.col.f32.f16.f16.f32 "
                    "{%0,%1,%2,%3},{%4,%5,%6,%7},{%8,%9},{%0,%1,%2,%3};"
                    : "+f"(sa[mt][nt][0]), "+f"(sa[mt][nt][1]),
                      "+f"(sa[mt][nt][2]), "+f"(sa[mt][nt][3])
                    : "r"(a[mt][0]), "r"(a[mt][1]), "r"(a[mt][2]), "r"(a[mt][3]),
                      "r"(b[nt][0]), "r"(b[nt][1]));
    }

    // scale + bias/mask + softmax + pack P (fp16)
    const float* bmw = bm + ((size_t)(head * 16 + (win & 15)) * NTOK) * 56;
    unsigned P[4][7][2];
    #pragma unroll
    for (int mt = 0; mt < 4; mt++) {
        int r0 = mt * 16 + g;
        int r1 = r0 + 8;
        // scale + bias
        #pragma unroll
        for (int nt = 0; nt < 7; nt++) {
            int c0 = nt * 8 + 2 * t4;
            float bv0 = (r0 < NTOK) ? bmw[r0 * 56 + c0]     : 0.0f;
            float bv1 = (r0 < NTOK) ? bmw[r0 * 56 + c0 + 1] : 0.0f;
            float bv2 = (r1 < NTOK) ? bmw[r1 * 56 + c0]     : 0.0f;
            float bv3 = (r1 < NTOK) ? bmw[r1 * 56 + c0 + 1] : 0.0f;
            sa[mt][nt][0] = sa[mt][nt][0] * ATT_SCALE + bv0;
            sa[mt][nt][1] = sa[mt][nt][1] * ATT_SCALE + bv1;
            sa[mt][nt][2] = sa[mt][nt][2] * ATT_SCALE + bv2;
            sa[mt][nt][3] = sa[mt][nt][3] * ATT_SCALE + bv3;
        }
        // row max (quad reduce over t4)
        float m0 = -1e30f, m1 = -1e30f;
        #pragma unroll
        for (int nt = 0; nt < 7; nt++) {
            m0 = fmaxf(m0, fmaxf(sa[mt][nt][0], sa[mt][nt][1]));
            m1 = fmaxf(m1, fmaxf(sa[mt][nt][2], sa[mt][nt][3]));
        }
        m0 = fmaxf(m0, __shfl_xor_sync(0xffffffffu, m0, 1));
        m0 = fmaxf(m0, __shfl_xor_sync(0xffffffffu, m0, 2));
        m1 = fmaxf(m1, __shfl_xor_sync(0xffffffffu, m1, 1));
        m1 = fmaxf(m1, __shfl_xor_sync(0xffffffffu, m1, 2));
        // exp + sum
        float s0 = 0.0f, s1 = 0.0f;
        #pragma unroll
        for (int nt = 0; nt < 7; nt++) {
            float e0 = __expf(sa[mt][nt][0] - m0);
            float e1 = __expf(sa[mt][nt][1] - m0);
            float e2 = __expf(sa[mt][nt][2] - m1);
            float e3 = __expf(sa[mt][nt][3] - m1);
            sa[mt][nt][0] = e0; sa[mt][nt][1] = e1;
            sa[mt][nt][2] = e2; sa[mt][nt][3] = e3;
            s0 += e0 + e1; s1 += e2 + e3;
        }
        s0 += __shfl_xor_sync(0xffffffffu, s0, 1);
        s0 += __shfl_xor_sync(0xffffffffu, s0, 2);
        s1 += __shfl_xor_sync(0xffffffffu, s1, 1);
        s1 += __shfl_xor_sync(0xffffffffu, s1, 2);
        float i0 = 1.0f / s0, i1 = 1.0f / s1;
        #pragma unroll
        for (int nt = 0; nt < 7; nt++) {
            __half2 p01 = __floats2half2_rn(sa[mt][nt][0] * i0, sa[mt][nt][1] * i0);
            __half2 p23 = __floats2half2_rn(sa[mt][nt][2] * i1, sa[mt][nt][3] * i1);
            P[mt][nt][0] = *(unsigned*)&p01;
            P[mt][nt][1] = *(unsigned*)&p23;
        }
    }

    // O = P @ V   (K dim 49 -> 4 k16 chunks, last half-padded with zeros)
    float oa[4][4][4];
    #pragma unroll
    for (int i = 0; i < 4; i++)
        #pragma unroll
        for (int j = 0; j < 4; j++)
            #pragma unroll
            for (int q = 0; q < 4; q++) oa[i][j][q] = 0.0f;

    #pragma unroll
    for (int kc = 0; kc < 4; kc++) {
        uint32_t kb = (uint32_t)(kc * 32);   // 16 halves
        unsigned vb[4][2];
        #pragma unroll
        for (int nt = 0; nt < 4; nt++)
            asm volatile(
                "ldmatrix.sync.aligned.m8n8.x2.shared.b16 {%0,%1}, [%2];"
                : "=r"(vb[nt][0]), "=r"(vb[nt][1]) : "r"(vf[nt] + kb));
        #pragma unroll
        for (int mt = 0; mt < 4; mt++) {
            unsigned pa0 = P[mt][2 * kc][0];
            unsigned pa1 = P[mt][2 * kc][1];
            unsigned pa2 = (kc < 3) ? P[mt][2 * kc + 1][0] : 0u;
            unsigned pa3 = (kc < 3) ? P[mt][2 * kc + 1][1] : 0u;
            #pragma unroll
            for (int nt = 0; nt < 4; nt++)
                asm volatile(
                    "mma.sync.aligned.m16n8k16.row.col.f32.f16.f16.f32 "
                    "{%0,%1,%2,%3},{%4,%5,%6,%7},{%8,%9},{%0,%1,%2,%3};"
                    : "+f"(oa[mt][nt][0]), "+f"(oa[mt][nt][1]),
                      "+f"(oa[mt][nt][2]), "+f"(oa[mt][nt][3])
                    : "r"(pa0), "r"(pa1), "r"(pa2), "r"(pa3),
                      "r"(vb[nt][0]), "r"(vb[nt][1]));
        }
    }

    // write O (fp16)
    __half* owp = ow + (size_t)win * NTOK * CC + head * HD;
    #pragma unroll
    for (int mt = 0; mt < 4; mt++) {
        int r0 = mt * 16 + g;
        int r1 = r0 + 8;
        #pragma unroll
        for (int nt = 0; nt < 4; nt++) {
            int c0 = nt * 8 + 2 * t4;
            if (r0 < NTOK)
                *(__half2*)(owp + (size_t)r0 * CC + c0) =
                    __floats2half2_rn(oa[mt][nt][0], oa[mt][nt][1]);
            if (r1 < NTOK)
                *(__half2*)(owp + (size_t)r1 * CC + c0) =
                    __floats2half2_rn(oa[mt][nt][2], oa[mt][nt][3]);
        }
    }
}

// ---------------- launch ----------------
extern "C" void kernel_launch(void* const* d_in, const int* in_sizes, int n_in,
                              void* d_out, int out_size)
{
    const float* x      = (const float*)d_in[0];
    const float* qkv_w  = (const float*)d_in[1];
    const float* qkv_b  = (const float*)d_in[2];
    const float* proj_w = (const float*)d_in[3];
    const float* proj_b = (const float*)d_in[4];
    const float* rpb    = (const float*)d_in[5];
    const float* n1g    = (const float*)d_in[6];
    const float* n1b    = (const float*)d_in[7];
    const float* n2g    = (const float*)d_in[8];
    const float* n2b    = (const float*)d_in[9];
    const float* fc1_w  = (const float*)d_in[10];
    const float* fc1_b  = (const float*)d_in[11];
    const float* fc2_w  = (const float*)d_in[12];
    const float* fc2_b  = (const float*)d_in[13];
    float* out = (float*)d_out;

    __half *xw, *qkvh, *ow, *ln2, *mid, *wh_qkv, *wh_proj, *wh_fc1, *wh_fc2;
    float *y, *bm; int* dmap;
    cudaGetSymbolAddress((void**)&xw,      g_xw);
    cudaGetSymbolAddress((void**)&qkvh,    g_qkvh);
    cudaGetSymbolAddress((void**)&ow,      g_ow);
    cudaGetSymbolAddress((void**)&y,       g_y);
    cudaGetSymbolAddress((void**)&ln2,     g_ln2);
    cudaGetSymbolAddress((void**)&mid,     g_mid);
    cudaGetSymbolAddress((void**)&dmap,    g_dmap);
    cudaGetSymbolAddress((void**)&bm,      g_bm);
    cudaGetSymbolAddress((void**)&wh_qkv,  g_wh_qkv);
    cudaGetSymbolAddress((void**)&wh_proj, g_wh_proj);
    cudaGetSymbolAddress((void**)&wh_fc1,  g_wh_fc1);
    cudaGetSymbolAddress((void**)&wh_fc2,  g_wh_fc2);

    cudaFuncSetAttribute(mma_gemm, cudaFuncAttributeMaxDynamicSharedMemorySize, SMEM_BYTES);
    cudaFuncSetAttribute(attn_mma_kernel, cudaFuncAttributeMaxDynamicSharedMemorySize, ATT_SMEM);

    // 0. weight convert/transpose + bias-mask table
    convw_kernel<<<dim3((3 * CC) / 32, CC / 32), dim3(32, 8)>>>(qkv_w, wh_qkv, CC, 3 * CC);
    convw_kernel<<<dim3(CC / 32, CC / 32),       dim3(32, 8)>>>(proj_w, wh_proj, CC, CC);
    convw_kernel<<<dim3(HID / 32, CC / 32),      dim3(32, 8)>>>(fc1_w, wh_fc1, CC, HID);
    convw_kernel<<<dim3(CC / 32, HID / 32),      dim3(32, 8)>>>(fc2_w, wh_fc2, HID, CC);
    bm_kernel<<<dim3(16, NHD), 256>>>(rpb, bm);

    // 1. LN1 + shift + window partition (fp16 out)
    ln_kernel<<<TOK, 96>>>(x, n1g, n1b, xw, 1);

    // 2. QKV -> fp16
    mma_gemm<<<dim3((3 * CC) / 128, TOK / 128), 256, SMEM_BYTES>>>(
        xw, wh_qkv, qkv_b, nullptr, qkvh, nullptr, nullptr, TOK, 3 * CC, CC, 0);

    // 3. Windowed attention (tensor-core) -> fp16
    attn_mma_kernel<<<(NWINS * NHD) / 4, 128, ATT_SMEM>>>(bm, ow);

    // 4. Proj + window reverse + residual -> fp32 y
    mma_gemm<<<dim3(CC / 128, TOK / 128), 256, SMEM_BYTES>>>(
        ow, wh_proj, proj_b, y, nullptr, x, dmap, TOK, CC, CC, 0);

    // 5. LN2 (fp16 out)
    ln_kernel<<<TOK, 96>>>(y, n2g, n2b, ln2, 0);

    // 6. FC1 + GELU -> fp16 mid
    mma_gemm<<<dim3(HID / 128, TOK / 128), 256, SMEM_BYTES>>>(
        ln2, wh_fc1, fc1_b, nullptr, mid, nullptr, nullptr, TOK, HID, CC, 1);

    // 7. FC2 + residual -> fp32 out
    mma_gemm<<<dim3(CC / 128, TOK / 128), 256, SMEM_BYTES>>>(
        mid, wh_fc2, fc2_b, out, nullptr, y, nullptr, TOK, CC, HID, 0);
}

// round 11
// speedup vs baseline: 2.7243x; 1.1408x over previous
#include <cuda_runtime.h>
#include <cuda_fp16.h>
#include <math.h>
#include <stdint.h>

// ---------------- problem constants ----------------
#define BB    64
#define HH    28
#define WW    28
#define CC    384
#define WS    7
#define SHIFT 3
#define NHD   12
#define HD    32
#define HID   1536
#define NWIN  16
#define NTOK  49
#define TOK   50176
#define NWINS 1024
#define ATT_SCALE 0.17677669529663687f

// ---------------- static scratch ----------------
__device__ __half g_xw  [(size_t)TOK * CC];
__device__ __half g_qkvh[(size_t)TOK * 3 * CC];
__device__ __half g_ow  [(size_t)TOK * CC];
__device__ float  g_y   [(size_t)TOK * CC];
__device__ __half g_ln2 [(size_t)TOK * CC];
__device__ __half g_mid [(size_t)TOK * HID];
__device__ int    g_dmap[TOK];
__device__ float  g_bm  [(size_t)NHD * 16 * NTOK * 56];
// fp16 transposed weights [N][K]
__device__ __half g_wh_qkv [(size_t)(3 * CC) * CC];
__device__ __half g_wh_proj[(size_t)CC * CC];
__device__ __half g_wh_fc1 [(size_t)HID * CC];
__device__ __half g_wh_fc2 [(size_t)CC * HID];

// ---------------- weight convert + transpose: fp32 [K][N] -> fp16 [N][K] ----------------
__global__ __launch_bounds__(256) void convw_kernel(
    const float* __restrict__ in, __half* __restrict__ out, int K, int N)
{
    __shared__ float t[32][33];
    int bx = blockIdx.x * 32, by = blockIdx.y * 32;
    int tx = threadIdx.x, ty = threadIdx.y;
    #pragma unroll
    for (int i = 0; i < 32; i += 8)
        t[ty + i][tx] = in[(size_t)(by + ty + i) * N + bx + tx];
    __syncthreads();
    #pragma unroll
    for (int i = 0; i < 32; i += 8)
        out[(size_t)(bx + ty + i) * K + by + tx] = __float2half_rn(t[tx][ty + i]);
}

// ---------------- bias + shift-mask precompute ----------------
__global__ __launch_bounds__(256) void bm_kernel(
    const float* __restrict__ rpb, float* __restrict__ bm)
{
    int wm   = blockIdx.x;
    int head = blockIdx.y;
    int wi = wm >> 2, wj = wm & 3;
    for (int idx = threadIdx.x; idx < NTOK * 56; idx += 256) {
        int n = idx / 56, m = idx - n * 56;
        float val;
        if (m >= NTOK) {
            val = -30000.0f;
        } else {
            int in_ = n / WS, jn = n % WS, im = m / WS, jm = m % WS;
            int rel = (in_ - im + WS - 1) * (2 * WS - 1) + (jn - jm + WS - 1);
            val = rpb[rel * NHD + head];
            int hn = wi * WS + in_, wn = wj * WS + jn;
            int hm = wi * WS + im, wmm = wj * WS + jm;
            int vn = (hn < HH - WS ? 0 : (hn < HH - SHIFT ? 1 : 2)) * 3
                   + (wn < WW - WS ? 0 : (wn < WW - SHIFT ? 1 : 2));
            int vm = (hm < HH - WS ? 0 : (hm < HH - SHIFT ? 1 : 2)) * 3
                   + (wmm < WW - WS ? 0 : (wmm < WW - SHIFT ? 1 : 2));
            if (vn != vm) val -= 100.0f;
        }
        bm[((size_t)(head * 16 + wm) * NTOK + n) * 56 + m] = val;
    }
}

// ---------------- LayerNorm, warp-per-row (8 rows / 256-thread block) ----------------
__global__ __launch_bounds__(256) void ln_kernel(
    const float* __restrict__ x, const float* __restrict__ g,
    const float* __restrict__ b, __half* __restrict__ out, int mode)
{
    int warp = threadIdx.x >> 5, lane = threadIdx.x & 31;
    int r = blockIdx.x * 8 + warp;
    int src = r;
    if (mode == 1) {
        int win  = r / NTOK;
        int n    = r - win * NTOK;
        int bidx = win >> 4;
        int widx = win & 15;
        int wi = widx >> 2, wj = widx & 3;
        int ph = n / WS, pw = n - ph * WS;
        int h = (wi * WS + ph + SHIFT) % HH;
        int w = (wj * WS + pw + SHIFT) % WW;
        src = bidx * (HH * WW) + h * WW + w;
        if (lane == 0) g_dmap[r] = src;
    }
    const float4* xr = (const float4*)(x + (size_t)src * CC);
    float4 v[3];
    float s = 0.0f, s2 = 0.0f;
    #pragma unroll
    for (int j = 0; j < 3; j++) {
        v[j] = xr[lane + 32 * j];
        s  += v[j].x + v[j].y + v[j].z + v[j].w;
        s2 += v[j].x * v[j].x + v[j].y * v[j].y + v[j].z * v[j].z + v[j].w * v[j].w;
    }
    #pragma unroll
    for (int o = 16; o; o >>= 1) {
        s  += __shfl_xor_sync(0xffffffffu, s,  o);
        s2 += __shfl_xor_sync(0xffffffffu, s2, o);
    }
    float mu  = s * (1.0f / CC);
    float inv = rsqrtf(s2 * (1.0f / CC) - mu * mu + 1e-5f);
    __half2* orow = (__half2*)(out + (size_t)r * CC);
    #pragma unroll
    for (int j = 0; j < 3; j++) {
        float4 gg = ((const float4*)g)[lane + 32 * j];
        float4 bb = ((const float4*)b)[lane + 32 * j];
        float ox = (v[j].x - mu) * inv * gg.x + bb.x;
        float oy = (v[j].y - mu) * inv * gg.y + bb.y;
        float oz = (v[j].z - mu) * inv * gg.z + bb.z;
        float ow_ = (v[j].w - mu) * inv * gg.w + bb.w;
        orow[2 * (lane + 32 * j)]     = __floats2half2_rn(ox, oy);
        orow[2 * (lane + 32 * j) + 1] = __floats2half2_rn(oz, ow_);
    }
}

// ---------------- fp16 GEMM (m16n8k16), KC=64, 3-stage cp.async, ldmatrix ----------------
// 128x128 CTA tile, 8 warps 2m x 4n, warp tile 64x32. Smem row = 64 halves
// padded to 72 (36 words): banks 4r mod 32 distinct over 8 rows -> LDSM clean.
#define KC 64
#define RSTR 72                           // halves per smem row
#define OP_H (128 * RSTR)                 // halves per operand per stage
#define STG_H (2 * OP_H)
#define STAGES 3
#define SMEM_BYTES (STAGES * STG_H * 2)   // 110592

__device__ __forceinline__ void cp16(uint32_t s, const void* g) {
    asm volatile("cp.async.cg.shared.global [%0], [%1], 16;" :: "r"(s), "l"(g));
}

__global__ __launch_bounds__(256, 2) void mma_gemm(
    const __half* __restrict__ A, const __half* __restrict__ Bt,
    const float* __restrict__ bias, float* __restrict__ Cf,
    __half* __restrict__ Ch,
    const float* __restrict__ addend, const int* __restrict__ rowmap,
    int M, int Nn, int K, int act)
{
    extern __shared__ __half sh[];
    uint32_t base = (uint32_t)__cvta_generic_to_shared(sh);

    int tid  = threadIdx.x;
    int warp = tid >> 5, lane = tid & 31;
    int g    = lane >> 2, t4 = lane & 3;
    int wm   = warp >> 2, wn = warp & 3;
    int tile_m = blockIdx.y * 128;
    int tile_n = blockIdx.x * 128;
    int nk = K / KC;

    // cp.async coords: 1024 16B chunks per operand, 4/thread
    int rr[4], cc[4];
    #pragma unroll
    for (int i = 0; i < 4; i++) {
        int c = tid + i * 256;
        rr[i] = c >> 3;  cc[i] = c & 7;
    }

    auto issue = [&](int tile) {
        int k0 = tile * KC;
        int s  = tile % STAGES;
        uint32_t sb = base + (uint32_t)(s * STG_H) * 2u;
        #pragma unroll
        for (int i = 0; i < 4; i++)
            cp16(sb + (uint32_t)(rr[i] * RSTR + cc[i] * 8) * 2u,
                 &A[(size_t)(tile_m + rr[i]) * K + k0 + cc[i] * 8]);
        #pragma unroll
        for (int i = 0; i < 4; i++)
            cp16(sb + (uint32_t)(OP_H + rr[i] * RSTR + cc[i] * 8) * 2u,
                 &Bt[(size_t)(tile_n + rr[i]) * K + k0 + cc[i] * 8]);
        asm volatile("cp.async.commit_group;");
    };

    // ldmatrix byte offsets within a stage
    uint32_t a_off[4];
    #pragma unroll
    for (int mt = 0; mt < 4; mt++)
        a_off[mt] = (uint32_t)(((wm * 64 + mt * 16 + (lane & 15)) * RSTR
                               + (lane >> 4) * 8) * 2);
    // B x4 over nt-pairs: row = wn*32 + p*16 + (lane>>4)*8 + (lane&7), chunk=(lane>>3)&1
    uint32_t b_off[2];
    #pragma unroll
    for (int p = 0; p < 2; p++)
        b_off[p] = (uint32_t)((OP_H + (wn * 32 + p * 16 + ((lane >> 4) << 3) + (lane & 7)) * RSTR
                              + ((lane >> 3) & 1) * 8) * 2);

    float acc[4][4][4];
    #pragma unroll
    for (int i = 0; i < 4; i++)
        #pragma unroll
        for (int j = 0; j < 4; j++)
            #pragma unroll
            for (int q = 0; q < 4; q++) acc[i][j][q] = 0.0f;

    issue(0);
    if (nk > 1) issue(1); else asm volatile("cp.async.commit_group;");

    for (int it = 0; it < nk; it++) {
        asm volatile("cp.async.wait_group 1;");
        __syncthreads();
        uint32_t sb = base + (uint32_t)((it % STAGES) * STG_H) * 2u;
        int nxt = it + 2;
        if (nxt < nk) issue(nxt);
        else asm volatile("cp.async.commit_group;");

        #pragma unroll
        for (int ks = 0; ks < 4; ks++) {
            uint32_t kb = (uint32_t)(ks * 32);   // 16 halves
            unsigned a[4][4], bfr[2][4];
            #pragma unroll
            for (int mt = 0; mt < 4; mt++)
                asm volatile(
                    "ldmatrix.sync.aligned.m8n8.x4.shared.b16 {%0,%1,%2,%3}, [%4];"
                    : "=r"(a[mt][0]), "=r"(a[mt][1]), "=r"(a[mt][2]), "=r"(a[mt][3])
                    : "r"(sb + a_off[mt] + kb));
            #pragma unroll
            for (int p = 0; p < 2; p++)
                asm volatile(
                    "ldmatrix.sync.aligned.m8n8.x4.shared.b16 {%0,%1,%2,%3}, [%4];"
                    : "=r"(bfr[p][0]), "=r"(bfr[p][1]), "=r"(bfr[p][2]), "=r"(bfr[p][3])
                    : "r"(sb + b_off[p] + kb));
            #pragma unroll
            for (int mt = 0; mt < 4; mt++)
                #pragma unroll
                for (int nt = 0; nt < 4; nt++) {
                    unsigned b0 = bfr[nt >> 1][(nt & 1) * 2];
                    unsigned b1 = bfr[nt >> 1][(nt & 1) * 2 + 1];
                    asm volatile(
                        "mma.sync.aligned.m16n8k16.row.col.f32.f16.f16.f32 "
                        "{%0,%1,%2,%3},{%4,%5,%6,%7},{%8,%9},{%0,%1,%2,%3};"
                        : "+f"(acc[mt][nt][0]), "+f"(acc[mt][nt][1]),
                          "+f"(acc[mt][nt][2]), "+f"(acc[mt][nt][3])
                        : "r"(a[mt][0]), "r"(a[mt][1]), "r"(a[mt][2]), "r"(a[mt][3]),
                          "r"(b0), "r"(b1));
                }
        }
    }

    // epilogue
    #pragma unroll
    for (int mt = 0; mt < 4; mt++) {
        int r0 = tile_m + wm * 64 + mt * 16 + g;
        int r1 = r0 + 8;
        int o0 = rowmap ? rowmap[r0] : r0;
        int o1 = rowmap ? rowmap[r1] : r1;
        #pragma unroll
        for (int nt = 0; nt < 4; nt++) {
            int c0 = tile_n + wn * 32 + nt * 8 + 2 * t4;
            float b0 = bias[c0], b1 = bias[c0 + 1];
            float v0 = acc[mt][nt][0] + b0, v1 = acc[mt][nt][1] + b1;
            float v2 = acc[mt][nt][2] + b0, v3 = acc[mt][nt][3] + b1;
            if (act == 1) {
                v0 = 0.5f * v0 * (1.0f + erff(v0 * 0.70710678118654752f));
                v1 = 0.5f * v1 * (1.0f + erff(v1 * 0.70710678118654752f));
                v2 = 0.5f * v2 * (1.0f + erff(v2 * 0.70710678118654752f));
                v3 = 0.5f * v3 * (1.0f + erff(v3 * 0.70710678118654752f));
            }
            size_t f0 = (size_t)o0 * Nn + c0;
            size_t f1 = (size_t)o1 * Nn + c0;
            if (addend) {
                v0 += addend[f0]; v1 += addend[f0 + 1];
                v2 += addend[f1]; v3 += addend[f1 + 1];
            }
            if (Ch) {
                *(__half2*)&Ch[f0] = __floats2half2_rn(v0, v1);
                *(__half2*)&Ch[f1] = __floats2half2_rn(v2, v3);
            } else {
                Cf[f0] = v0; Cf[f0 + 1] = v1;
                Cf[f1] = v2; Cf[f1 + 1] = v3;
            }
        }
    }
}

// ---------------- mma windowed attention: 1 warp = 1 (window, head) ----------------
#define AW_H   7168
#define AQ_OFF 0
#define AK_OFF 2560
#define AV_OFF 4800
#define ATT_SMEM (4 * AW_H * 2)

__global__ __launch_bounds__(128) void attn_mma_kernel(
    const float* __restrict__ bm, __half* __restrict__ ow)
{
    extern __shared__ __half ash[];
    int tid  = threadIdx.x;
    int warp = tid >> 5, lane = tid & 31;
    int unit = blockIdx.x * 4 + warp;
    int head = unit >> 10;
    int win  = unit & 1023;
    int g = lane >> 2, t4 = lane & 3;

    __half* ws = ash + warp * AW_H;
    uint32_t wsu = (uint32_t)__cvta_generic_to_shared(ws);

    {
        uint4 zz = make_uint4(0, 0, 0, 0);
        uint4* p = (uint4*)ws;
        #pragma unroll
        for (int i = 0; i < AW_H / 8 / 32; i++)
            p[lane + i * 32] = zz;
    }
    __syncwarp();

    const __half* qb = g_qkvh + (size_t)win * NTOK * (3 * CC) + head * HD;
    for (int c = lane; c < NTOK * 4; c += 32) {
        int row = c >> 2, cq = c & 3;
        const __half* src = qb + (size_t)row * (3 * CC) + cq * 8;
        *(uint4*)(ws + AQ_OFF + row * 40 + cq * 8) = *(const uint4*)(src);
        *(uint4*)(ws + AK_OFF + row * 40 + cq * 8) = *(const uint4*)(src + CC);
    }
    for (int c = lane; c < NTOK * 16; c += 32) {
        int m = c >> 4, d2 = c & 15;
        __half2 v = *(const __half2*)(qb + (size_t)m * (3 * CC) + 2 * CC + d2 * 2);
        ws[AV_OFF + (2 * d2)     * 72 + m] = __low2half(v);
        ws[AV_OFF + (2 * d2 + 1) * 72 + m] = __high2half(v);
    }
    __syncwarp();

    uint32_t qa[4], kf[7], vf[4];
    #pragma unroll
    for (int mt = 0; mt < 4; mt++)
        qa[mt] = wsu + (uint32_t)((AQ_OFF + (mt * 16 + (lane & 15)) * 40
                                   + (lane >> 4) * 8) * 2);
    #pragma unroll
    for (int nt = 0; nt < 7; nt++)
        kf[nt] = wsu + (uint32_t)((AK_OFF + (nt * 8 + (lane & 7)) * 40
                                   + ((lane >> 3) & 1) * 8) * 2);
    #pragma unroll
    for (int nt = 0; nt < 4; nt++)
        vf[nt] = wsu + (uint32_t)((AV_OFF + (nt * 8 + (lane & 7)) * 72
                                   + ((lane >> 3) & 1) * 8) * 2);

    float sa[4][7][4];
    #pragma unroll
    for (int i = 0; i < 4; i++)
        #pragma unroll
        for (int j = 0; j < 7; j++)
            #pragma unroll
            for (int q = 0; q < 4; q++) sa[i][j][q] = 0.0f;

    #pragma unroll
    for (int ks = 0; ks < 2; ks++) {
        uint32_t kb = (uint32_t)(ks * 32);
        unsigned a[4][4], b[7][2];
        #pragma unroll
        for (int mt = 0; mt < 4; mt++)
            asm volatile(
                "ldmatrix.sync.aligned.m8n8.x4.shared.b16 {%0,%1,%2,%3}, [%4];"
                : "=r"(a[mt][0]), "=r"(a[mt][1]), "=r"(a[mt][2]), "=r"(a[mt][3])
                : "r"(qa[mt] + kb));
        #pragma unroll
        for (int nt = 0; nt < 7; nt++)
            asm volatile(
                "ldmatrix.sync.aligned.m8n8.x2.shared.b16 {%0,%1}, [%2];"
                : "=r"(b[nt][0]), "=r"(b[nt][1]) : "r"(kf[nt] + kb));
        #pragma unroll
        for (int mt = 0; mt < 4; mt++)
            #pragma unroll
            for (int nt = 0; nt < 7; nt++)
                asm volatile(
                    "mma.sync.aligned.m16n8k16.row.col.f32.f16.f16.f32 "
                    "{%0,%1,%2,%3},{%4,%5,%6,%7},{%8,%9},{%0,%1,%2,%3};"
                    : "+f"(sa[mt][nt][0]), "+f"(sa[mt][nt][1]),
                      "+f"(sa[mt][nt][2]), "+f"(sa[mt][nt][3])
                    : "r"(a[mt][0]), "r"(a[mt][1]), "r"(a[mt][2]), "r"(a[mt][3]),
                      "r"(b[nt][0]), "r"(b[nt][1]));
    }

    const float* bmw = bm + ((size_t)(head * 16 + (win & 15)) * NTOK) * 56;
    unsigned P[4][7][2];
    #pragma unroll
    for (int mt = 0; mt < 4; mt++) {
        int r0 = mt * 16 + g;
        int r1 = r0 + 8;
        #pragma unroll
        for (int nt = 0; nt < 7; nt++) {
            int c0 = nt * 8 + 2 * t4;
            float bv0 = (r0 < NTOK) ? bmw[r0 * 56 + c0]     : 0.0f;
            float bv1 = (r0 < NTOK) ? bmw[r0 * 56 + c0 + 1] : 0.0f;
            float bv2 = (r1 < NTOK) ? bmw[r1 * 56 + c0]     : 0.0f;
            float bv3 = (r1 < NTOK) ? bmw[r1 * 56 + c0 + 1] : 0.0f;
            sa[mt][nt][0] = sa[mt][nt][0] * ATT_SCALE + bv0;
            sa[mt][nt][1] = sa[mt][nt][1] * ATT_SCALE + bv1;
            sa[mt][nt][2] = sa[mt][nt][2] * ATT_SCALE + bv2;
            sa[mt][nt][3] = sa[mt][nt][3] * ATT_SCALE + bv3;
        }
        float m0 = -1e30f, m1 = -1e30f;
        #pragma unroll
        for (int nt = 0; nt < 7; nt++) {
            m0 = fmaxf(m0, fmaxf(sa[mt][nt][0], sa[mt][nt][1]));
            m1 = fmaxf(m1, fmaxf(sa[mt][nt][2], sa[mt][nt][3]));
        }
        m0 = fmaxf(m0, __shfl_xor_sync(0xffffffffu, m0, 1));
        m0 = fmaxf(m0, __shfl_xor_sync(0xffffffffu, m0, 2));
        m1 = fmaxf(m1, __shfl_xor_sync(0xffffffffu, m1, 1));
        m1 = fmaxf(m1, __shfl_xor_sync(0xffffffffu, m1, 2));
        float s0 = 0.0f, s1 = 0.0f;
        #pragma unroll
        for (int nt = 0; nt < 7; nt++) {
            float e0 = __expf(sa[mt][nt][0] - m0);
            float e1 = __expf(sa[mt][nt][1] - m0);
            float e2 = __expf(sa[mt][nt][2] - m1);
            float e3 = __expf(sa[mt][nt][3] - m1);
            sa[mt][nt][0] = e0; sa[mt][nt][1] = e1;
            sa[mt][nt][2] = e2; sa[mt][nt][3] = e3;
            s0 += e0 + e1; s1 += e2 + e3;
        }
        s0 += __shfl_xor_sync(0xffffffffu, s0, 1);
        s0 += __shfl_xor_sync(0xffffffffu, s0, 2);
        s1 += __shfl_xor_sync(0xffffffffu, s1, 1);
        s1 += __shfl_xor_sync(0xffffffffu, s1, 2);
        float i0 = 1.0f / s0, i1 = 1.0f / s1;
        #pragma unroll
        for (int nt = 0; nt < 7; nt++) {
            __half2 p01 = __floats2half2_rn(sa[mt][nt][0] * i0, sa[mt][nt][1] * i0);
            __half2 p23 = __floats2half2_rn(sa[mt][nt][2] * i1, sa[mt][nt][3] * i1);
            P[mt][nt][0] = *(unsigned*)&p01;
            P[mt][nt][1] = *(unsigned*)&p23;
        }
    }

    float oa[4][4][4];
    #pragma unroll
    for (int i = 0; i < 4; i++)
        #pragma unroll
        for (int j = 0; j < 4; j++)
            #pragma unroll
            for (int q = 0; q < 4; q++) oa[i][j][q] = 0.0f;

    #pragma unroll
    for (int kc = 0; kc < 4; kc++) {
        uint32_t kb = (uint32_t)(kc * 32);
        unsigned vb[4][2];
        #pragma unroll
        for (int nt = 0; nt < 4; nt++)
            asm volatile(
                "ldmatrix.sync.aligned.m8n8.x2.shared.b16 {%0,%1}, [%2];"
                : "=r"(vb[nt][0]), "=r"(vb[nt][1]) : "r"(vf[nt] + kb));
        #pragma unroll
        for (int mt = 0; mt < 4; mt++) {
            unsigned pa0 = P[mt][2 * kc][0];
            unsigned pa1 = P[mt][2 * kc][1];
            unsigned pa2 = (kc < 3) ? P[mt][2 * kc + 1][0] : 0u;
            unsigned pa3 = (kc < 3) ? P[mt][2 * kc + 1][1] : 0u;
            #pragma unroll
            for (int nt = 0; nt < 4; nt++)
                asm volatile(
                    "mma.sync.aligned.m16n8k16.row.col.f32.f16.f16.f32 "
                    "{%0,%1,%2,%3},{%4,%5,%6,%7},{%8,%9},{%0,%1,%2,%3};"
                    : "+f"(oa[mt][nt][0]), "+f"(oa[mt][nt][1]),
                      "+f"(oa[mt][nt][2]), "+f"(oa[mt][nt][3])
                    : "r"(pa0), "r"(pa1), "r"(pa2), "r"(pa3),
                      "r"(vb[nt][0]), "r"(vb[nt][1]));
        }
    }

    __half* owp = ow + (size_t)win * NTOK * CC + head * HD;
    #pragma unroll
    for (int mt = 0; mt < 4; mt++) {
        int r0 = mt * 16 + g;
        int r1 = r0 + 8;
        #pragma unroll
        for (int nt = 0; nt < 4; nt++) {
            int c0 = nt * 8 + 2 * t4;
            if (r0 < NTOK)
                *(__half2*)(owp + (size_t)r0 * CC + c0) =
                    __floats2half2_rn(oa[mt][nt][0], oa[mt][nt][1]);
            if (r1 < NTOK)
                *(__half2*)(owp + (size_t)r1 * CC + c0) =
                    __floats2half2_rn(oa[mt][nt][2], oa[mt][nt][3]);
        }
    }
}

// ---------------- launch ----------------
extern "C" void kernel_launch(void* const* d_in, const int* in_sizes, int n_in,
                              void* d_out, int out_size)
{
    const float* x      = (const float*)d_in[0];
    const float* qkv_w  = (const float*)d_in[1];
    const float* qkv_b  = (const float*)d_in[2];
    const float* proj_w = (const float*)d_in[3];
    const float* proj_b = (const float*)d_in[4];
    const float* rpb    = (const float*)d_in[5];
    const float* n1g    = (const float*)d_in[6];
    const float* n1b    = (const float*)d_in[7];
    const float* n2g    = (const float*)d_in[8];
    const float* n2b    = (const float*)d_in[9];
    const float* fc1_w  = (const float*)d_in[10];
    const float* fc1_b  = (const float*)d_in[11];
    const float* fc2_w  = (const float*)d_in[12];
    const float* fc2_b  = (const float*)d_in[13];
    float* out = (float*)d_out;

    __half *xw, *qkvh, *ow, *ln2, *mid, *wh_qkv, *wh_proj, *wh_fc1, *wh_fc2;
    float *y, *bm; int* dmap;
    cudaGetSymbolAddress((void**)&xw,      g_xw);
    cudaGetSymbolAddress((void**)&qkvh,    g_qkvh);
    cudaGetSymbolAddress((void**)&ow,      g_ow);
    cudaGetSymbolAddress((void**)&y,       g_y);
    cudaGetSymbolAddress((void**)&ln2,     g_ln2);
    cudaGetSymbolAddress((void**)&mid,     g_mid);
    cudaGetSymbolAddress((void**)&dmap,    g_dmap);
    cudaGetSymbolAddress((void**)&bm,      g_bm);
    cudaGetSymbolAddress((void**)&wh_qkv,  g_wh_qkv);
    cudaGetSymbolAddress((void**)&wh_proj, g_wh_proj);
    cudaGetSymbolAddress((void**)&wh_fc1,  g_wh_fc1);
    cudaGetSymbolAddress((void**)&wh_fc2,  g_wh_fc2);

    cudaFuncSetAttribute(mma_gemm, cudaFuncAttributeMaxDynamicSharedMemorySize, SMEM_BYTES);
    cudaFuncSetAttribute(attn_mma_kernel, cudaFuncAttributeMaxDynamicSharedMemorySize, ATT_SMEM);

    // 0. weight convert/transpose + bias-mask table
    convw_kernel<<<dim3((3 * CC) / 32, CC / 32), dim3(32, 8)>>>(qkv_w, wh_qkv, CC, 3 * CC);
    convw_kernel<<<dim3(CC / 32, CC / 32),       dim3(32, 8)>>>(proj_w, wh_proj, CC, CC);
    convw_kernel<<<dim3(HID / 32, CC / 32),      dim3(32, 8)>>>(fc1_w, wh_fc1, CC, HID);
    convw_kernel<<<dim3(CC / 32, HID / 32),      dim3(32, 8)>>>(fc2_w, wh_fc2, HID, CC);
    bm_kernel<<<dim3(16, NHD), 256>>>(rpb, bm);

    // 1. LN1 + shift + window partition (fp16 out)
    ln_kernel<<<TOK / 8, 256>>>(x, n1g, n1b, xw, 1);

    // 2. QKV -> fp16
    mma_gemm<<<dim3((3 * CC) / 128, TOK / 128), 256, SMEM_BYTES>>>(
        xw, wh_qkv, qkv_b, nullptr, qkvh, nullptr, nullptr, TOK, 3 * CC, CC, 0);

    // 3. Windowed attention (tensor-core) -> fp16
    attn_mma_kernel<<<(NWINS * NHD) / 4, 128, ATT_SMEM>>>(bm, ow);

    // 4. Proj + window reverse + residual -> fp32 y
    mma_gemm<<<dim3(CC / 128, TOK / 128), 256, SMEM_BYTES>>>(
        ow, wh_proj, proj_b, y, nullptr, x, dmap, TOK, CC, CC, 0);

    // 5. LN2 (fp16 out)
    ln_kernel<<<TOK / 8, 256>>>(y, n2g, n2b, ln2, 0);

    // 6. FC1 + GELU -> fp16 mid
    mma_gemm<<<dim3(HID / 128, TOK / 128), 256, SMEM_BYTES>>>(
        ln2, wh_fc1, fc1_b, nullptr, mid, nullptr, nullptr, TOK, HID, CC, 1);

    // 7. FC2 + residual -> fp32 out
    mma_gemm<<<dim3(CC / 128, TOK / 128), 256, SMEM_BYTES>>>(
        mid, wh_fc2, fc2_b, out, nullptr, y, nullptr, TOK, CC, HID, 0);
}

// round 12
// speedup vs baseline: 2.7446x; 1.0075x over previous
#include <cuda_runtime.h>
#include <cuda_fp16.h>
#include <math.h>
#include <stdint.h>

// ---------------- problem constants ----------------
#define BB    64
#define HH    28
#define WW    28
#define CC    384
#define WS    7
#define SHIFT 3
#define NHD   12
#define HD    32
#define HID   1536
#define NWIN  16
#define NTOK  49
#define TOK   50176
#define NWINS 1024
#define ATT_SCALE 0.17677669529663687f

// ---------------- static scratch ----------------
__device__ __half g_xw  [(size_t)TOK * CC];
__device__ __half g_qkvh[(size_t)TOK * 3 * CC];
__device__ __half g_ow  [(size_t)TOK * CC];
__device__ float  g_y   [(size_t)TOK * CC];
__device__ __half g_ln2 [(size_t)TOK * CC];
__device__ __half g_mid [(size_t)TOK * HID];
__device__ int    g_dmap[TOK];
__device__ float  g_bm  [(size_t)NHD * 16 * NTOK * 56];
__device__ __half g_wh_qkv [(size_t)(3 * CC) * CC];
__device__ __half g_wh_proj[(size_t)CC * CC];
__device__ __half g_wh_fc1 [(size_t)HID * CC];
__device__ __half g_wh_fc2 [(size_t)CC * HID];

// ---------------- all 4 weight converts in ONE launch (z-indexed) ----------------
__global__ __launch_bounds__(256) void convw_all(
    const float* __restrict__ i0, const float* __restrict__ i1,
    const float* __restrict__ i2, const float* __restrict__ i3,
    __half* __restrict__ o0, __half* __restrict__ o1,
    __half* __restrict__ o2, __half* __restrict__ o3)
{
    int z = blockIdx.z;
    const float* in; __half* out; int K, N;
    if (z == 0)      { in = i0; out = o0; K = CC;  N = 3 * CC; }
    else if (z == 1) { in = i1; out = o1; K = CC;  N = CC; }
    else if (z == 2) { in = i2; out = o2; K = CC;  N = HID; }
    else             { in = i3; out = o3; K = HID; N = CC; }
    int bx = blockIdx.x * 32, by = blockIdx.y * 32;
    if (bx >= N || by >= K) return;
    __shared__ float t[32][33];
    int tx = threadIdx.x, ty = threadIdx.y;
    #pragma unroll
    for (int i = 0; i < 32; i += 8)
        t[ty + i][tx] = in[(size_t)(by + ty + i) * N + bx + tx];
    __syncthreads();
    #pragma unroll
    for (int i = 0; i < 32; i += 8)
        out[(size_t)(bx + ty + i) * K + by + tx] = __float2half_rn(t[tx][ty + i]);
}

// ---------------- bias + shift-mask precompute ----------------
__global__ __launch_bounds__(256) void bm_kernel(
    const float* __restrict__ rpb, float* __restrict__ bm)
{
    int wm   = blockIdx.x;
    int head = blockIdx.y;
    int wi = wm >> 2, wj = wm & 3;
    for (int idx = threadIdx.x; idx < NTOK * 56; idx += 256) {
        int n = idx / 56, m = idx - n * 56;
        float val;
        if (m >= NTOK) {
            val = -30000.0f;
        } else {
            int in_ = n / WS, jn = n % WS, im = m / WS, jm = m % WS;
            int rel = (in_ - im + WS - 1) * (2 * WS - 1) + (jn - jm + WS - 1);
            val = rpb[rel * NHD + head];
            int hn = wi * WS + in_, wn = wj * WS + jn;
            int hm = wi * WS + im, wmm = wj * WS + jm;
            int vn = (hn < HH - WS ? 0 : (hn < HH - SHIFT ? 1 : 2)) * 3
                   + (wn < WW - WS ? 0 : (wn < WW - SHIFT ? 1 : 2));
            int vm = (hm < HH - WS ? 0 : (hm < HH - SHIFT ? 1 : 2)) * 3
                   + (wmm < WW - WS ? 0 : (wmm < WW - SHIFT ? 1 : 2));
            if (vn != vm) val -= 100.0f;
        }
        bm[((size_t)(head * 16 + wm) * NTOK + n) * 56 + m] = val;
    }
}

// ---------------- LayerNorm, warp-per-row ----------------
__global__ __launch_bounds__(256) void ln_kernel(
    const float* __restrict__ x, const float* __restrict__ g,
    const float* __restrict__ b, __half* __restrict__ out, int mode)
{
    int warp = threadIdx.x >> 5, lane = threadIdx.x & 31;
    int r = blockIdx.x * 8 + warp;
    int src = r;
    if (mode == 1) {
        int win  = r / NTOK;
        int n    = r - win * NTOK;
        int bidx = win >> 4;
        int widx = win & 15;
        int wi = widx >> 2, wj = widx & 3;
        int ph = n / WS, pw = n - ph * WS;
        int h = (wi * WS + ph + SHIFT) % HH;
        int w = (wj * WS + pw + SHIFT) % WW;
        src = bidx * (HH * WW) + h * WW + w;
        if (lane == 0) g_dmap[r] = src;
    }
    const float4* xr = (const float4*)(x + (size_t)src * CC);
    float4 v[3];
    float s = 0.0f, s2 = 0.0f;
    #pragma unroll
    for (int j = 0; j < 3; j++) {
        v[j] = xr[lane + 32 * j];
        s  += v[j].x + v[j].y + v[j].z + v[j].w;
        s2 += v[j].x * v[j].x + v[j].y * v[j].y + v[j].z * v[j].z + v[j].w * v[j].w;
    }
    #pragma unroll
    for (int o = 16; o; o >>= 1) {
        s  += __shfl_xor_sync(0xffffffffu, s,  o);
        s2 += __shfl_xor_sync(0xffffffffu, s2, o);
    }
    float mu  = s * (1.0f / CC);
    float inv = rsqrtf(s2 * (1.0f / CC) - mu * mu + 1e-5f);
    __half2* orow = (__half2*)(out + (size_t)r * CC);
    #pragma unroll
    for (int j = 0; j < 3; j++) {
        float4 gg = ((const float4*)g)[lane + 32 * j];
        float4 bb = ((const float4*)b)[lane + 32 * j];
        float ox = (v[j].x - mu) * inv * gg.x + bb.x;
        float oy = (v[j].y - mu) * inv * gg.y + bb.y;
        float oz = (v[j].z - mu) * inv * gg.z + bb.z;
        float ow_ = (v[j].w - mu) * inv * gg.w + bb.w;
        orow[2 * (lane + 32 * j)]     = __floats2half2_rn(ox, oy);
        orow[2 * (lane + 32 * j) + 1] = __floats2half2_rn(oz, ow_);
    }
}

// ---------------- fp16 GEMM (m16n8k16), KC=64, 3-stage cp.async, ldmatrix ----------------
#define KC 64
#define RSTR 72
#define OP_H (128 * RSTR)
#define STG_H (2 * OP_H)
#define STAGES 3
#define SMEM_BYTES (STAGES * STG_H * 2)

__device__ __forceinline__ void cp16(uint32_t s, const void* g) {
    asm volatile("cp.async.cg.shared.global [%0], [%1], 16;" :: "r"(s), "l"(g));
}

__global__ __launch_bounds__(256, 2) void mma_gemm(
    const __half* __restrict__ A, const __half* __restrict__ Bt,
    const float* __restrict__ bias, float* __restrict__ Cf,
    __half* __restrict__ Ch,
    const float* __restrict__ addend, const int* __restrict__ rowmap,
    int M, int Nn, int K, int act)
{
    extern __shared__ __half sh[];
    uint32_t base = (uint32_t)__cvta_generic_to_shared(sh);

    int tid  = threadIdx.x;
    int warp = tid >> 5, lane = tid & 31;
    int g    = lane >> 2, t4 = lane & 3;
    int wm   = warp >> 2, wn = warp & 3;
    int tile_m = blockIdx.y * 128;
    int tile_n = blockIdx.x * 128;
    int nk = K / KC;

    int rr[4], cc[4];
    #pragma unroll
    for (int i = 0; i < 4; i++) {
        int c = tid + i * 256;
        rr[i] = c >> 3;  cc[i] = c & 7;
    }

    auto issue = [&](int tile) {
        int k0 = tile * KC;
        int s  = tile % STAGES;
        uint32_t sb = base + (uint32_t)(s * STG_H) * 2u;
        #pragma unroll
        for (int i = 0; i < 4; i++)
            cp16(sb + (uint32_t)(rr[i] * RSTR + cc[i] * 8) * 2u,
                 &A[(size_t)(tile_m + rr[i]) * K + k0 + cc[i] * 8]);
        #pragma unroll
        for (int i = 0; i < 4; i++)
            cp16(sb + (uint32_t)(OP_H + rr[i] * RSTR + cc[i] * 8) * 2u,
                 &Bt[(size_t)(tile_n + rr[i]) * K + k0 + cc[i] * 8]);
        asm volatile("cp.async.commit_group;");
    };

    uint32_t a_off[4];
    #pragma unroll
    for (int mt = 0; mt < 4; mt++)
        a_off[mt] = (uint32_t)(((wm * 64 + mt * 16 + (lane & 15)) * RSTR
                               + (lane >> 4) * 8) * 2);
    uint32_t b_off[2];
    #pragma unroll
    for (int p = 0; p < 2; p++)
        b_off[p] = (uint32_t)((OP_H + (wn * 32 + p * 16 + ((lane >> 4) << 3) + (lane & 7)) * RSTR
                              + ((lane >> 3) & 1) * 8) * 2);

    float acc[4][4][4];
    #pragma unroll
    for (int i = 0; i < 4; i++)
        #pragma unroll
        for (int j = 0; j < 4; j++)
            #pragma unroll
            for (int q = 0; q < 4; q++) acc[i][j][q] = 0.0f;

    issue(0);
    if (nk > 1) issue(1); else asm volatile("cp.async.commit_group;");

    for (int it = 0; it < nk; it++) {
        asm volatile("cp.async.wait_group 1;");
        __syncthreads();
        uint32_t sb = base + (uint32_t)((it % STAGES) * STG_H) * 2u;
        int nxt = it + 2;
        if (nxt < nk) issue(nxt);
        else asm volatile("cp.async.commit_group;");

        #pragma unroll
        for (int ks = 0; ks < 4; ks++) {
            uint32_t kb = (uint32_t)(ks * 32);
            unsigned a[4][4], bfr[2][4];
            #pragma unroll
            for (int mt = 0; mt < 4; mt++)
                asm volatile(
                    "ldmatrix.sync.aligned.m8n8.x4.shared.b16 {%0,%1,%2,%3}, [%4];"
                    : "=r"(a[mt][0]), "=r"(a[mt][1]), "=r"(a[mt][2]), "=r"(a[mt][3])
                    : "r"(sb + a_off[mt] + kb));
            #pragma unroll
            for (int p = 0; p < 2; p++)
                asm volatile(
                    "ldmatrix.sync.aligned.m8n8.x4.shared.b16 {%0,%1,%2,%3}, [%4];"
                    : "=r"(bfr[p][0]), "=r"(bfr[p][1]), "=r"(bfr[p][2]), "=r"(bfr[p][3])
                    : "r"(sb + b_off[p] + kb));
            #pragma unroll
            for (int mt = 0; mt < 4; mt++)
                #pragma unroll
                for (int nt = 0; nt < 4; nt++) {
                    unsigned b0 = bfr[nt >> 1][(nt & 1) * 2];
                    unsigned b1 = bfr[nt >> 1][(nt & 1) * 2 + 1];
                    asm volatile(
                        "mma.sync.aligned.m16n8k16.row.col.f32.f16.f16.f32 "
                        "{%0,%1,%2,%3},{%4,%5,%6,%7},{%8,%9},{%0,%1,%2,%3};"
                        : "+f"(acc[mt][nt][0]), "+f"(acc[mt][nt][1]),
                          "+f"(acc[mt][nt][2]), "+f"(acc[mt][nt][3])
                        : "r"(a[mt][0]), "r"(a[mt][1]), "r"(a[mt][2]), "r"(a[mt][3]),
                          "r"(b0), "r"(b1));
                }
        }
    }

    #pragma unroll
    for (int mt = 0; mt < 4; mt++) {
        int r0 = tile_m + wm * 64 + mt * 16 + g;
        int r1 = r0 + 8;
        int o0 = rowmap ? rowmap[r0] : r0;
        int o1 = rowmap ? rowmap[r1] : r1;
        #pragma unroll
        for (int nt = 0; nt < 4; nt++) {
            int c0 = tile_n + wn * 32 + nt * 8 + 2 * t4;
            float b0 = bias[c0], b1 = bias[c0 + 1];
            float v0 = acc[mt][nt][0] + b0, v1 = acc[mt][nt][1] + b1;
            float v2 = acc[mt][nt][2] + b0, v3 = acc[mt][nt][3] + b1;
            if (act == 1) {
                v0 = 0.5f * v0 * (1.0f + erff(v0 * 0.70710678118654752f));
                v1 = 0.5f * v1 * (1.0f + erff(v1 * 0.70710678118654752f));
                v2 = 0.5f * v2 * (1.0f + erff(v2 * 0.70710678118654752f));
                v3 = 0.5f * v3 * (1.0f + erff(v3 * 0.70710678118654752f));
            }
            size_t f0 = (size_t)o0 * Nn + c0;
            size_t f1 = (size_t)o1 * Nn + c0;
            if (addend) {
                v0 += addend[f0]; v1 += addend[f0 + 1];
                v2 += addend[f1]; v3 += addend[f1 + 1];
            }
            if (Ch) {
                *(__half2*)&Ch[f0] = __floats2half2_rn(v0, v1);
                *(__half2*)&Ch[f1] = __floats2half2_rn(v2, v3);
            } else {
                Cf[f0] = v0; Cf[f0 + 1] = v1;
                Cf[f1] = v2; Cf[f1 + 1] = v3;
            }
        }
    }
}

// ---------------- mma windowed attention, sequential mt-tiles (low regs) ----------------
#define AW_H   7168
#define AQ_OFF 0
#define AK_OFF 2560
#define AV_OFF 4800
#define ATT_SMEM (4 * AW_H * 2)   // 57344 B/block; 4 blocks/SM fit in 228KB

__global__ __launch_bounds__(128) void attn_mma_kernel(
    const float* __restrict__ bm, __half* __restrict__ ow)
{
    extern __shared__ __half ash[];
    int tid  = threadIdx.x;
    int warp = tid >> 5, lane = tid & 31;
    int unit = blockIdx.x * 4 + warp;
    int head = unit >> 10;
    int win  = unit & 1023;
    int g = lane >> 2, t4 = lane & 3;

    __half* ws = ash + warp * AW_H;
    uint32_t wsu = (uint32_t)__cvta_generic_to_shared(ws);

    {
        uint4 zz = make_uint4(0, 0, 0, 0);
        uint4* p = (uint4*)ws;
        #pragma unroll
        for (int i = 0; i < AW_H / 8 / 32; i++)
            p[lane + i * 32] = zz;
    }
    __syncwarp();

    const __half* qb = g_qkvh + (size_t)win * NTOK * (3 * CC) + head * HD;
    for (int c = lane; c < NTOK * 4; c += 32) {
        int row = c >> 2, cq = c & 3;
        const __half* src = qb + (size_t)row * (3 * CC) + cq * 8;
        *(uint4*)(ws + AQ_OFF + row * 40 + cq * 8) = *(const uint4*)(src);
        *(uint4*)(ws + AK_OFF + row * 40 + cq * 8) = *(const uint4*)(src + CC);
    }
    for (int c = lane; c < NTOK * 16; c += 32) {
        int m = c >> 4, d2 = c & 15;
        __half2 v = *(const __half2*)(qb + (size_t)m * (3 * CC) + 2 * CC + d2 * 2);
        ws[AV_OFF + (2 * d2)     * 72 + m] = __low2half(v);
        ws[AV_OFF + (2 * d2 + 1) * 72 + m] = __high2half(v);
    }
    __syncwarp();

    // K fragments held in registers (reused for every mt tile)
    unsigned kfr[2][7][2];
    #pragma unroll
    for (int ks = 0; ks < 2; ks++) {
        uint32_t kb = (uint32_t)(ks * 32);
        #pragma unroll
        for (int nt = 0; nt < 7; nt++) {
            uint32_t addr = wsu + (uint32_t)((AK_OFF + (nt * 8 + (lane & 7)) * 40
                                   + ((lane >> 3) & 1) * 8) * 2) + kb;
            asm volatile(
                "ldmatrix.sync.aligned.m8n8.x2.shared.b16 {%0,%1}, [%2];"
                : "=r"(kfr[ks][nt][0]), "=r"(kfr[ks][nt][1]) : "r"(addr));
        }
    }
    uint32_t vf[4];
    #pragma unroll
    for (int nt = 0; nt < 4; nt++)
        vf[nt] = wsu + (uint32_t)((AV_OFF + (nt * 8 + (lane & 7)) * 72
                                   + ((lane >> 3) & 1) * 8) * 2);

    const float* bmw = bm + ((size_t)(head * 16 + (win & 15)) * NTOK) * 56;
    __half* owp = ow + (size_t)win * NTOK * CC + head * HD;

    #pragma unroll
    for (int mt = 0; mt < 4; mt++) {
        // S = Q_mt @ K^T
        float sa[7][4];
        #pragma unroll
        for (int j = 0; j < 7; j++)
            #pragma unroll
            for (int q = 0; q < 4; q++) sa[j][q] = 0.0f;

        #pragma unroll
        for (int ks = 0; ks < 2; ks++) {
            unsigned a[4];
            uint32_t addr = wsu + (uint32_t)(((mt * 16 + (lane & 15)) * 40
                                   + (lane >> 4) * 8) * 2) + (uint32_t)(ks * 32);
            asm volatile(
                "ldmatrix.sync.aligned.m8n8.x4.shared.b16 {%0,%1,%2,%3}, [%4];"
                : "=r"(a[0]), "=r"(a[1]), "=r"(a[2]), "=r"(a[3]) : "r"(addr));
            #pragma unroll
            for (int nt = 0; nt < 7; nt++)
                asm volatile(
                    "mma.sync.aligned.m16n8k16.row.col.f32.f16.f16.f32 "
                    "{%0,%1,%2,%3},{%4,%5,%6,%7},{%8,%9},{%0,%1,%2,%3};"
                    : "+f"(sa[nt][0]), "+f"(sa[nt][1]),
                      "+f"(sa[nt][2]), "+f"(sa[nt][3])
                    : "r"(a[0]), "r"(a[1]), "r"(a[2]), "r"(a[3]),
                      "r"(kfr[ks][nt][0]), "r"(kfr[ks][nt][1]));
        }

        // scale + bias/mask + softmax + pack P
        int r0 = mt * 16 + g;
        int r1 = r0 + 8;
        #pragma unroll
        for (int nt = 0; nt < 7; nt++) {
            int c0 = nt * 8 + 2 * t4;
            float2 bv01 = (r0 < NTOK) ? *(const float2*)&bmw[r0 * 56 + c0]
                                      : make_float2(0.f, 0.f);
            float2 bv23 = (r1 < NTOK) ? *(const float2*)&bmw[r1 * 56 + c0]
                                      : make_float2(0.f, 0.f);
            sa[nt][0] = sa[nt][0] * ATT_SCALE + bv01.x;
            sa[nt][1] = sa[nt][1] * ATT_SCALE + bv01.y;
            sa[nt][2] = sa[nt][2] * ATT_SCALE + bv23.x;
            sa[nt][3] = sa[nt][3] * ATT_SCALE + bv23.y;
        }
        float m0 = -1e30f, m1 = -1e30f;
        #pragma unroll
        for (int nt = 0; nt < 7; nt++) {
            m0 = fmaxf(m0, fmaxf(sa[nt][0], sa[nt][1]));
            m1 = fmaxf(m1, fmaxf(sa[nt][2], sa[nt][3]));
        }
        m0 = fmaxf(m0, __shfl_xor_sync(0xffffffffu, m0, 1));
        m0 = fmaxf(m0, __shfl_xor_sync(0xffffffffu, m0, 2));
        m1 = fmaxf(m1, __shfl_xor_sync(0xffffffffu, m1, 1));
        m1 = fmaxf(m1, __shfl_xor_sync(0xffffffffu, m1, 2));
        float s0 = 0.0f, s1 = 0.0f;
        #pragma unroll
        for (int nt = 0; nt < 7; nt++) {
            float e0 = __expf(sa[nt][0] - m0);
            float e1 = __expf(sa[nt][1] - m0);
            float e2 = __expf(sa[nt][2] - m1);
            float e3 = __expf(sa[nt][3] - m1);
            sa[nt][0] = e0; sa[nt][1] = e1;
            sa[nt][2] = e2; sa[nt][3] = e3;
            s0 += e0 + e1; s1 += e2 + e3;
        }
        s0 += __shfl_xor_sync(0xffffffffu, s0, 1);
        s0 += __shfl_xor_sync(0xffffffffu, s0, 2);
        s1 += __shfl_xor_sync(0xffffffffu, s1, 1);
        s1 += __shfl_xor_sync(0xffffffffu, s1, 2);
        float i0 = 1.0f / s0, i1 = 1.0f / s1;
        unsigned P[7][2];
        #pragma unroll
        for (int nt = 0; nt < 7; nt++) {
            __half2 p01 = __floats2half2_rn(sa[nt][0] * i0, sa[nt][1] * i0);
            __half2 p23 = __floats2half2_rn(sa[nt][2] * i1, sa[nt][3] * i1);
            P[nt][0] = *(unsigned*)&p01;
            P[nt][1] = *(unsigned*)&p23;
        }

        // O_mt = P @ V
        float oa[4][4];
        #pragma unroll
        for (int j = 0; j < 4; j++)
            #pragma unroll
            for (int q = 0; q < 4; q++) oa[j][q] = 0.0f;

        #pragma unroll
        for (int kc = 0; kc < 4; kc++) {
            uint32_t kb = (uint32_t)(kc * 32);
            unsigned vb[4][2];
            #pragma unroll
            for (int nt = 0; nt < 4; nt++)
                asm volatile(
                    "ldmatrix.sync.aligned.m8n8.x2.shared.b16 {%0,%1}, [%2];"
                    : "=r"(vb[nt][0]), "=r"(vb[nt][1]) : "r"(vf[nt] + kb));
            unsigned pa0 = P[2 * kc][0];
            unsigned pa1 = P[2 * kc][1];
            unsigned pa2 = (kc < 3) ? P[2 * kc + 1][0] : 0u;
            unsigned pa3 = (kc < 3) ? P[2 * kc + 1][1] : 0u;
            #pragma unroll
            for (int nt = 0; nt < 4; nt++)
                asm volatile(
                    "mma.sync.aligned.m16n8k16.row.col.f32.f16.f16.f32 "
                    "{%0,%1,%2,%3},{%4,%5,%6,%7},{%8,%9},{%0,%1,%2,%3};"
                    : "+f"(oa[nt][0]), "+f"(oa[nt][1]),
                      "+f"(oa[nt][2]), "+f"(oa[nt][3])
                    : "r"(pa0), "r"(pa1), "r"(pa2), "r"(pa3),
                      "r"(vb[nt][0]), "r"(vb[nt][1]));
        }

        #pragma unroll
        for (int nt = 0; nt < 4; nt++) {
            int c0 = nt * 8 + 2 * t4;
            if (r0 < NTOK)
                *(__half2*)(owp + (size_t)r0 * CC + c0) =
                    __floats2half2_rn(oa[nt][0], oa[nt][1]);
            if (r1 < NTOK)
                *(__half2*)(owp + (size_t)r1 * CC + c0) =
                    __floats2half2_rn(oa[nt][2], oa[nt][3]);
        }
    }
}

// ---------------- launch ----------------
extern "C" void kernel_launch(void* const* d_in, const int* in_sizes, int n_in,
                              void* d_out, int out_size)
{
    const float* x      = (const float*)d_in[0];
    const float* qkv_w  = (const float*)d_in[1];
    const float* qkv_b  = (const float*)d_in[2];
    const float* proj_w = (const float*)d_in[3];
    const float* proj_b = (const float*)d_in[4];
    const float* rpb    = (const float*)d_in[5];
    const float* n1g    = (const float*)d_in[6];
    const float* n1b    = (const float*)d_in[7];
    const float* n2g    = (const float*)d_in[8];
    const float* n2b    = (const float*)d_in[9];
    const float* fc1_w  = (const float*)d_in[10];
    const float* fc1_b  = (const float*)d_in[11];
    const float* fc2_w  = (const float*)d_in[12];
    const float* fc2_b  = (const float*)d_in[13];
    float* out = (float*)d_out;

    __half *xw, *qkvh, *ow, *ln2, *mid, *wh_qkv, *wh_proj, *wh_fc1, *wh_fc2;
    float *y, *bm; int* dmap;
    cudaGetSymbolAddress((void**)&xw,      g_xw);
    cudaGetSymbolAddress((void**)&qkvh,    g_qkvh);
    cudaGetSymbolAddress((void**)&ow,      g_ow);
    cudaGetSymbolAddress((void**)&y,       g_y);
    cudaGetSymbolAddress((void**)&ln2,     g_ln2);
    cudaGetSymbolAddress((void**)&mid,     g_mid);
    cudaGetSymbolAddress((void**)&dmap,    g_dmap);
    cudaGetSymbolAddress((void**)&bm,      g_bm);
    cudaGetSymbolAddress((void**)&wh_qkv,  g_wh_qkv);
    cudaGetSymbolAddress((void**)&wh_proj, g_wh_proj);
    cudaGetSymbolAddress((void**)&wh_fc1,  g_wh_fc1);
    cudaGetSymbolAddress((void**)&wh_fc2,  g_wh_fc2);

    cudaFuncSetAttribute(mma_gemm, cudaFuncAttributeMaxDynamicSharedMemorySize, SMEM_BYTES);
    cudaFuncSetAttribute(attn_mma_kernel, cudaFuncAttributeMaxDynamicSharedMemorySize, ATT_SMEM);

    // 0. weight convert/transpose (one launch) + bias-mask table
    convw_all<<<dim3(48, 48, 4), dim3(32, 8)>>>(
        qkv_w, proj_w, fc1_w, fc2_w, wh_qkv, wh_proj, wh_fc1, wh_fc2);
    bm_kernel<<<dim3(16, NHD), 256>>>(rpb, bm);

    // 1. LN1 + shift + window partition (fp16 out)
    ln_kernel<<<TOK / 8, 256>>>(x, n1g, n1b, xw, 1);

    // 2. QKV -> fp16
    mma_gemm<<<dim3((3 * CC) / 128, TOK / 128), 256, SMEM_BYTES>>>(
        xw, wh_qkv, qkv_b, nullptr, qkvh, nullptr, nullptr, TOK, 3 * CC, CC, 0);

    // 3. Windowed attention (tensor-core) -> fp16
    attn_mma_kernel<<<(NWINS * NHD) / 4, 128, ATT_SMEM>>>(bm, ow);

    // 4. Proj + window reverse + residual -> fp32 y   (6th launch: ncu captures this)
    mma_gemm<<<dim3(CC / 128, TOK / 128), 256, SMEM_BYTES>>>(
        ow, wh_proj, proj_b, y, nullptr, x, dmap, TOK, CC, CC, 0);

    // 5. LN2 (fp16 out)
    ln_kernel<<<TOK / 8, 256>>>(y, n2g, n2b, ln2, 0);

    // 6. FC1 + GELU -> fp16 mid
    mma_gemm<<<dim3(HID / 128, TOK / 128), 256, SMEM_BYTES>>>(
        ln2, wh_fc1, fc1_b, nullptr, mid, nullptr, nullptr, TOK, HID, CC, 1);

    // 7. FC2 + residual -> fp32 out
    mma_gemm<<<dim3(CC / 128, TOK / 128), 256, SMEM_BYTES>>>(
        mid, wh_fc2, fc2_b, out, nullptr, y, nullptr, TOK, CC, HID, 0);
}